// round 11
// baseline (speedup 1.0000x reference)
#include <cuda_runtime.h>
#include <cuda_bf16.h>
#include <cstdint>

#define Bv 32
#define Nv 512
#define Hv 8
#define BHv 256

// ---------------- scratch ----------------
__device__ float g_Wh   [(size_t)BHv*Nv*64];
__device__ float g_ssrc [BHv*Nv];
__device__ float g_sdst [BHv*Nv];
__device__ int   g_perm1[BHv*Nv];
__device__ float g_B1a  [BHv*Nv];
__device__ float g_B2a  [BHv*Nv];
__device__ int   g_k1   [BHv*Nv];
__device__ float g_A1a  [BHv*Nv];
__device__ float g_A2a  [BHv*Nv];
__device__ float g_inv1 [BHv*Nv];

__device__ float g_x    [(size_t)Bv*Nv*512];
__device__ float g_Wh2  [(size_t)Bv*Nv*64];
__device__ float g_s2src[Bv*Nv];
__device__ float g_s2dst[Bv*Nv];
__device__ int   g_perm2[Bv*Nv];
__device__ float g_B1b  [Bv*Nv];
__device__ float g_B2b  [Bv*Nv];
__device__ int   g_k2   [Bv*Nv];
__device__ float g_A1b  [Bv*Nv];
__device__ float g_A2b  [Bv*Nv];
__device__ float g_inv2 [Bv*Nv];

__device__ float g_z    [(size_t)Bv*Nv*64];
__device__ float g_part [(size_t)256*32*256];
__device__ float g_z2   [32*256];
__device__ float g_z3   [32*256];

// =====================================================================
// Split-bf16 tensor-core GEMM, 64-row tiles, register-prefetch pipeline.
// C[64,64] tile = A[64,K] @ W[K,64];  3x mma: AhWh + AlWh + AhWl.
// Warps: (wid&3) -> 16-row band, (wid>>2) -> 32-col half.
// Fused row reductions s1 = C@av, s2 = C@bv (cross-warp smem reduce).
// =====================================================================
__device__ __forceinline__ void mma_bf16(float c[4],
        unsigned a0, unsigned a1, unsigned a2, unsigned a3,
        unsigned b0, unsigned b1) {
    asm volatile(
        "mma.sync.aligned.m16n8k16.row.col.f32.bf16.bf16.f32 "
        "{%0,%1,%2,%3}, {%4,%5,%6,%7}, {%8,%9}, {%0,%1,%2,%3};\n"
        : "+f"(c[0]), "+f"(c[1]), "+f"(c[2]), "+f"(c[3])
        : "r"(a0), "r"(a1), "r"(a2), "r"(a3), "r"(b0), "r"(b1));
}

#define SMEM_GEMM ((2*64*72 + 2*64*72) * 2)   // 36864 bytes

template<int NCH, bool HEADS>
__global__ __launch_bounds__(256) void k_gemm(const float* __restrict__ A, int lda,
                       const float* __restrict__ W,
                       const float* __restrict__ av, const float* __restrict__ bvv,
                       float* __restrict__ outC,
                       float* __restrict__ s1, float* __restrict__ s2) {
    extern __shared__ __align__(16) unsigned char smem_raw[];
    __nv_bfloat16* Ah  = (__nv_bfloat16*)smem_raw;     // [64][72]
    __nv_bfloat16* Al  = Ah  + 64*72;
    __nv_bfloat16* Whs = Al  + 64*72;                  // [64][72] transposed [o][f]
    __nv_bfloat16* Wls = Whs + 64*72;
    __shared__ float sred[2][2][64];

    int tid = threadIdx.x;
    int row0 = blockIdx.x * 64;
    int h = HEADS ? blockIdx.y : 0;
    const float* Wbase = HEADS ? (W + h*4096) : W;
    const float* avp = HEADS ? (av + h*64) : av;
    const float* bvp = HEADS ? (bvv + h*64) : bvv;
    size_t base_out = HEADS ? ((size_t)(row0 >> 9)*4096 + (size_t)h*512 + (row0 & 511))
                            : (size_t)row0;

    int lane = tid & 31, wid = tid >> 5;
    int g = lane >> 2, t = lane & 3;
    int mw = (wid & 3) * 16;      // row band
    int nh = (wid >> 2) * 32;     // col half

    float acc[4][4];
    #pragma unroll
    for (int nt = 0; nt < 4; ++nt)
        #pragma unroll
        for (int j = 0; j < 4; ++j) acc[nt][j] = 0.f;

    int ldf4 = lda >> 2;
    const float4* Abase = (const float4*)(A + (size_t)row0 * lda);

    float4 ra[4];
    float  rwv[16];
    // prefetch chunk 0
    #pragma unroll
    for (int p = 0; p < 4; ++p) {
        int i = tid + p*256;
        ra[p] = Abase[(size_t)(i >> 4) * ldf4 + (i & 15)];
    }
    #pragma unroll
    for (int p = 0; p < 16; ++p) rwv[p] = Wbase[tid + p*256];

    for (int ch = 0; ch < NCH; ++ch) {
        __syncthreads();      // previous mma done; smem free
        // convert + store staged regs
        #pragma unroll
        for (int p = 0; p < 4; ++p) {
            int i = tid + p*256;
            int r = i >> 4, c4 = i & 15;
            float4 v = ra[p];
            __nv_bfloat16 h0 = __float2bfloat16_rn(v.x);
            __nv_bfloat16 h1 = __float2bfloat16_rn(v.y);
            __nv_bfloat16 h2 = __float2bfloat16_rn(v.z);
            __nv_bfloat16 h3 = __float2bfloat16_rn(v.w);
            __nv_bfloat16 l0 = __float2bfloat16_rn(v.x - __bfloat162float(h0));
            __nv_bfloat16 l1 = __float2bfloat16_rn(v.y - __bfloat162float(h1));
            __nv_bfloat16 l2 = __float2bfloat16_rn(v.z - __bfloat162float(h2));
            __nv_bfloat16 l3 = __float2bfloat16_rn(v.w - __bfloat162float(h3));
            int base = r*72 + c4*4;
            __nv_bfloat162 hh0; hh0.x = h0; hh0.y = h1;
            __nv_bfloat162 hh1; hh1.x = h2; hh1.y = h3;
            __nv_bfloat162 ll0; ll0.x = l0; ll0.y = l1;
            __nv_bfloat162 ll1; ll1.x = l2; ll1.y = l3;
            *(__nv_bfloat162*)&Ah[base]     = hh0;
            *(__nv_bfloat162*)&Ah[base + 2] = hh1;
            *(__nv_bfloat162*)&Al[base]     = ll0;
            *(__nv_bfloat162*)&Al[base + 2] = ll1;
        }
        #pragma unroll
        for (int p = 0; p < 16; ++p) {
            int i = tid + p*256;
            int f = i >> 6, o = i & 63;
            float v = rwv[p];
            __nv_bfloat16 hi = __float2bfloat16_rn(v);
            Whs[o*72 + f] = hi;
            Wls[o*72 + f] = __float2bfloat16_rn(v - __bfloat162float(hi));
        }
        __syncthreads();
        // prefetch next chunk (overlaps with mma below)
        if (ch + 1 < NCH) {
            #pragma unroll
            for (int p = 0; p < 4; ++p) {
                int i = tid + p*256;
                ra[p] = Abase[(size_t)(i >> 4) * ldf4 + (ch+1)*16 + (i & 15)];
            }
            #pragma unroll
            for (int p = 0; p < 16; ++p) rwv[p] = Wbase[(ch+1)*4096 + tid + p*256];
        }
        // mma on staged chunk
        #pragma unroll
        for (int ks = 0; ks < 4; ++ks) {
            int ka = ks*16 + t*2;
            unsigned ah0 = *(const unsigned*)&Ah[(mw+g  )*72 + ka];
            unsigned ah1 = *(const unsigned*)&Ah[(mw+g+8)*72 + ka];
            unsigned ah2 = *(const unsigned*)&Ah[(mw+g  )*72 + ka + 8];
            unsigned ah3 = *(const unsigned*)&Ah[(mw+g+8)*72 + ka + 8];
            unsigned al0 = *(const unsigned*)&Al[(mw+g  )*72 + ka];
            unsigned al1 = *(const unsigned*)&Al[(mw+g+8)*72 + ka];
            unsigned al2 = *(const unsigned*)&Al[(mw+g  )*72 + ka + 8];
            unsigned al3 = *(const unsigned*)&Al[(mw+g+8)*72 + ka + 8];
            #pragma unroll
            for (int nt = 0; nt < 4; ++nt) {
                int ob = nh + nt*8 + g;
                unsigned bh0 = *(const unsigned*)&Whs[ob*72 + ka];
                unsigned bh1 = *(const unsigned*)&Whs[ob*72 + ka + 8];
                unsigned bl0 = *(const unsigned*)&Wls[ob*72 + ka];
                unsigned bl1 = *(const unsigned*)&Wls[ob*72 + ka + 8];
                mma_bf16(acc[nt], ah0, ah1, ah2, ah3, bh0, bh1);
                mma_bf16(acc[nt], al0, al1, al2, al3, bh0, bh1);
                mma_bf16(acc[nt], ah0, ah1, ah2, ah3, bl0, bl1);
            }
        }
    }

    // epilogue: store C + fused row reductions
    size_t rA = base_out + mw + g;
    size_t rB = rA + 8;
    float p1A = 0.f, p2A = 0.f, p1B = 0.f, p2B = 0.f;
    #pragma unroll
    for (int nt = 0; nt < 4; ++nt) {
        int col = nh + nt*8 + t*2;
        float a0 = avp[col], a1 = avp[col+1];
        float b0 = bvp[col], b1 = bvp[col+1];
        *(float2*)&outC[rA*64 + col] = make_float2(acc[nt][0], acc[nt][1]);
        *(float2*)&outC[rB*64 + col] = make_float2(acc[nt][2], acc[nt][3]);
        p1A += acc[nt][0]*a0 + acc[nt][1]*a1;
        p2A += acc[nt][0]*b0 + acc[nt][1]*b1;
        p1B += acc[nt][2]*a0 + acc[nt][3]*a1;
        p2B += acc[nt][2]*b0 + acc[nt][3]*b1;
    }
    #pragma unroll
    for (int d = 1; d <= 2; d <<= 1) {
        p1A += __shfl_xor_sync(0xffffffffu, p1A, d);
        p2A += __shfl_xor_sync(0xffffffffu, p2A, d);
        p1B += __shfl_xor_sync(0xffffffffu, p1B, d);
        p2B += __shfl_xor_sync(0xffffffffu, p2B, d);
    }
    int nhi = wid >> 2;
    if (t == 0) {
        sred[0][nhi][mw + g]     = p1A;
        sred[0][nhi][mw + g + 8] = p1B;
        sred[1][nhi][mw + g]     = p2A;
        sred[1][nhi][mw + g + 8] = p2B;
    }
    __syncthreads();
    if (tid < 64) {
        s1[base_out + tid] = sred[0][0][tid] + sred[0][1][tid];
        s2[base_out + tid] = sred[1][0][tid] + sred[1][1][tid];
    }
}

// =====================================================================
// K2 (templated): 64-bit-packed bitonic sort + warp scans + thresholds
// =====================================================================
template <int STAGE>
__global__ void k_sort() {
    const float* ssrc = STAGE ? g_s2src : g_ssrc;
    const float* sdst = STAGE ? g_s2dst : g_sdst;
    int*   perm  = STAGE ? g_perm2 : g_perm1;
    float* B1o   = STAGE ? g_B1b   : g_B1a;
    float* B2o   = STAGE ? g_B2b   : g_B2a;
    int*   kout  = STAGE ? g_k2    : g_k1;
    float* A1o   = STAGE ? g_A1b   : g_A1a;
    float* A2o   = STAGE ? g_A2b   : g_A2a;
    float* invo  = STAGE ? g_inv2  : g_inv1;

    __shared__ unsigned long long sx[512];
    __shared__ float skey[512];
    __shared__ float sD1[513], sD2[513];
    __shared__ float wsum1[16], wsum2[16];

    int bh = blockIdx.x, tid = threadIdx.x, base = bh * 512;
    const unsigned FULL = 0xffffffffu;

    float fv = sdst[base + tid];
    unsigned kb = __float_as_uint(fv);
    kb = (kb & 0x80000000u) ? ~kb : (kb | 0x80000000u);
    unsigned long long v = ((unsigned long long)kb << 32) | (unsigned)tid;

    for (int k = 2; k <= 512; k <<= 1) {
        bool up = ((tid & k) == 0);
        for (int j = k >> 1; j > 0; j >>= 1) {
            unsigned long long w;
            if (j >= 32) {
                sx[tid] = v; __syncthreads();
                w = sx[tid ^ j]; __syncthreads();
            } else {
                w = __shfl_xor_sync(FULL, v, j);
            }
            bool takeMin = (((tid & j) == 0) == up);
            v = takeMin ? (v < w ? v : w) : (v > w ? v : w);
        }
    }
    unsigned kb2 = (unsigned)(v >> 32);
    kb2 = (kb2 & 0x80000000u) ? (kb2 & 0x7fffffffu) : ~kb2;
    float tj = __uint_as_float(kb2);
    int srcidx = (int)(v & 0xffffffffu);
    skey[tid] = tj;
    __syncthreads();
    float maxt = skey[511];

    float b1 = __expf(tj - maxt);
    float b2 = __expf(0.2f * (tj - maxt));
    perm[base + tid] = srcidx;
    B1o[base + tid] = b1; B2o[base + tid] = b2;

    int lane = tid & 31, wid = tid >> 5;
    float s1 = b1, s2 = b2;
    #pragma unroll
    for (int d = 1; d < 32; d <<= 1) {
        float t1 = __shfl_up_sync(FULL, s1, d);
        float t2 = __shfl_up_sync(FULL, s2, d);
        if (lane >= d) { s1 += t1; s2 += t2; }
    }
    if (lane == 31) { wsum1[wid] = s1; wsum2[wid] = s2; }
    __syncthreads();
    if (tid < 16) {
        float a = wsum1[tid], c = wsum2[tid];
        #pragma unroll
        for (int d = 1; d < 16; d <<= 1) {
            float t = __shfl_up_sync(0x0000ffffu, a, d);
            float u = __shfl_up_sync(0x0000ffffu, c, d);
            if (tid >= d) { a += t; c += u; }
        }
        wsum1[tid] = a; wsum2[tid] = c;
    }
    __syncthreads();
    float off1 = wid ? wsum1[wid-1] : 0.f;
    float off2 = wid ? wsum2[wid-1] : 0.f;
    sD1[tid + 1] = s1 + off1;
    sD2[tid + 1] = s2 + off2;
    if (tid == 0) { sD1[0] = 0.f; sD2[0] = 0.f; }
    __syncthreads();

    float D1tot = sD1[512];
    float s = ssrc[base + tid];
    float thr = -s;
    int lo = 0, hi = 512;
    while (lo < hi) { int mid = (lo + hi) >> 1; if (skey[mid] <= thr) lo = mid + 1; else hi = mid; }
    float val = s + maxt;
    float m = val > 0.f ? val : 0.2f * val;
    float a1 = __expf(val - m);
    float a2 = __expf(0.2f * val - m);
    float den = a1 * (D1tot - sD1[lo]) + a2 * sD2[lo];
    kout[base + tid] = lo;
    A1o[base + tid] = a1; A2o[base + tid] = a2;
    invo[base + tid] = 1.f / den;
}

// =====================================================================
// K3 (templated): vector prefix sums + emission, 8-col blocks (~46KB smem)
// grid (nbh, 8) x 512
// =====================================================================
template <int STAGE>
__global__ void k_attn() {
    const float* Wh    = STAGE ? g_Wh2   : g_Wh;
    const int*   perm  = STAGE ? g_perm2 : g_perm1;
    const float* B1    = STAGE ? g_B1b   : g_B1a;
    const float* B2    = STAGE ? g_B2b   : g_B2a;
    const int*   kidx  = STAGE ? g_k2    : g_k1;
    const float* A1    = STAGE ? g_A1b   : g_A1a;
    const float* A2    = STAGE ? g_A2b   : g_A2a;
    const float* invd  = STAGE ? g_inv2  : g_inv1;
    float*       out   = STAGE ? g_z     : g_x;
    const int    Hn    = STAGE ? 1 : 8;
    const int    ld    = STAGE ? 64 : 512;

    extern __shared__ float sm[];
    float* P1  = sm;                   // 513*9
    float* P2  = P1 + 513*9;
    float* Ct1 = P2 + 513*9;           // 64*8
    float* Ct2 = Ct1 + 512;
    float* sB1 = Ct2 + 512;            // 512
    float* sB2 = sB1 + 512;
    int*   sperm = (int*)(sB2 + 512);  // 512

    int bh = blockIdx.x, cb = blockIdx.y;
    int tid = threadIdx.x;
    int base = bh * 512;
    int colbase = cb * 8;
    sB1[tid] = B1[base + tid];
    sB2[tid] = B2[base + tid];
    sperm[tid] = perm[base + tid];
    __syncthreads();

    int o = tid & 7, c = tid >> 3;     // c in [0,64)
    {
        float run1 = 0.f, run2 = 0.f;
        int pos0 = c * 8;
        const float* whb = Wh + (size_t)base * 64 + colbase + o;
        #pragma unroll
        for (int rr = 0; rr < 8; ++rr) {
            int pos = pos0 + rr;
            P1[pos*9 + o] = run1; P2[pos*9 + o] = run2;
            float w = whb[(size_t)sperm[pos] * 64];
            run1 = fmaf(sB1[pos], w, run1);
            run2 = fmaf(sB2[pos], w, run2);
        }
        Ct1[c*8 + o] = run1; Ct2[c*8 + o] = run2;
    }
    __syncthreads();
    {
        float off1 = 0.f, off2 = 0.f, tot1 = 0.f, tot2 = 0.f;
        #pragma unroll 8
        for (int cc = 0; cc < 64; ++cc) {
            float v1 = Ct1[cc*8 + o], v2 = Ct2[cc*8 + o];
            if (cc < c) { off1 += v1; off2 += v2; }
            tot1 += v1; tot2 += v2;
        }
        int pos0 = c * 8;
        #pragma unroll
        for (int rr = 0; rr < 8; ++rr) {
            P1[(pos0+rr)*9 + o] += off1;
            P2[(pos0+rr)*9 + o] += off2;
        }
        if (c == 0) { P1[512*9 + o] = tot1; P2[512*9 + o] = tot2; }
    }
    __syncthreads();
    int b = bh / Hn, h = bh % Hn;
    size_t outbase = (size_t)b * 512 * ld + (size_t)h * 64 + colbase + o;
    float t1 = P1[512*9 + o];
    #pragma unroll
    for (int it = 0; it < 8; ++it) {
        int i = c + it * 64;
        int k = kidx[base + i];
        float a1 = A1[base + i], a2 = A2[base + i], inv = invd[base + i];
        float p1 = P1[k*9 + o], p2 = P2[k*9 + o];
        float valo = (a1 * (t1 - p1) + a2 * p2) * inv;
        if (!STAGE) valo = valo > 0.f ? valo : (__expf(valo) - 1.f);
        out[outbase + (size_t)i * ld] = valo;
    }
}

// =====================================================================
// K5: fc1 partials with transposed z staging (broadcast float4 LDS)
// grid (64 kchunks, 4 colblocks) x 256, 72KB smem
// =====================================================================
__global__ void k_fc1(const float* __restrict__ fc1_w) {
    extern __shared__ float zs[];   // [512][36] transposed: zs[kk*36 + r]
    int kc = blockIdx.x, cb = blockIdx.y;
    int tid = threadIdx.x;
    int c = tid & 63, ks = tid >> 6;
    int k0 = kc * 512;
    for (int i = tid; i < 32*512; i += 256) {
        int rr = i >> 9, kk = i & 511;
        zs[kk*36 + rr] = g_z[(size_t)rr*32768 + k0 + kk];
    }
    __syncthreads();
    float acc[32];
    #pragma unroll
    for (int r = 0; r < 32; ++r) acc[r] = 0.f;
    const float* wp = fc1_w + (size_t)(k0 + ks*128)*256 + cb*64 + c;
    for (int kk = 0; kk < 128; ++kk) {
        float w = wp[(size_t)kk * 256];
        const float* zc = zs + (ks*128 + kk)*36;
        #pragma unroll
        for (int r4 = 0; r4 < 8; ++r4) {
            float4 z4 = *(const float4*)&zc[r4*4];
            acc[r4*4+0] = fmaf(z4.x, w, acc[r4*4+0]);
            acc[r4*4+1] = fmaf(z4.y, w, acc[r4*4+1]);
            acc[r4*4+2] = fmaf(z4.z, w, acc[r4*4+2]);
            acc[r4*4+3] = fmaf(z4.w, w, acc[r4*4+3]);
        }
    }
    int pidx = kc*4 + ks;
    for (int r = 0; r < 32; ++r)
        g_part[((size_t)pidx*32 + r)*256 + cb*64 + c] = acc[r];
}

__global__ void k_fc1r(const float* __restrict__ fc1_b) {
    int r = blockIdx.x; int c = threadIdx.x;
    float s = 0.f;
    for (int p = 0; p < 256; ++p) s += g_part[((size_t)p*32 + r)*256 + c];
    s += fc1_b[c];
    g_z2[r*256 + c] = s > 0.f ? s : 0.f;
}

__global__ void k_fc2(const float* __restrict__ w, const float* __restrict__ bias) {
    __shared__ float zr[256];
    int r = blockIdx.x; int c = threadIdx.x;
    zr[c] = g_z2[r*256 + c];
    __syncthreads();
    float s = bias[c];
    for (int k = 0; k < 256; ++k) s = fmaf(zr[k], w[(size_t)k*256 + c], s);
    g_z3[r*256 + c] = s > 0.f ? s : 0.f;
}

__global__ void k_fc3(const float* __restrict__ w, const float* __restrict__ bias,
                      float* __restrict__ out) {
    int r = blockIdx.x; int tid = threadIdx.x;
    int a = tid >> 5, lane = tid & 31;
    float s = 0.f;
    for (int k = lane; k < 256; k += 32) s = fmaf(g_z3[r*256 + k], w[k*4 + a], s);
    #pragma unroll
    for (int d = 16; d > 0; d >>= 1) s += __shfl_down_sync(0xffffffffu, s, d);
    if (lane == 0) out[r*4 + a] = tanhf(s + bias[a]);
}

// =====================================================================
extern "C" void kernel_launch(void* const* d_in, const int* in_sizes, int n_in,
                              void* d_out, int out_size) {
    const float* state     = (const float*)d_in[0];
    const float* W_heads   = (const float*)d_in[1];
    const float* a_src     = (const float*)d_in[2];
    const float* a_dst     = (const float*)d_in[3];
    const float* W_out     = (const float*)d_in[4];
    const float* a_out_src = (const float*)d_in[5];
    const float* a_out_dst = (const float*)d_in[6];
    const float* fc1_w     = (const float*)d_in[7];
    const float* fc1_b     = (const float*)d_in[8];
    const float* fc2_w     = (const float*)d_in[9];
    const float* fc2_b     = (const float*)d_in[10];
    const float* fc3_w     = (const float*)d_in[11];
    const float* fc3_b     = (const float*)d_in[12];
    float* out = (float*)d_out;

    float* pWh   = nullptr; cudaGetSymbolAddress((void**)&pWh,   g_Wh);
    float* pss   = nullptr; cudaGetSymbolAddress((void**)&pss,   g_ssrc);
    float* psd   = nullptr; cudaGetSymbolAddress((void**)&psd,   g_sdst);
    float* px    = nullptr; cudaGetSymbolAddress((void**)&px,    g_x);
    float* pWh2  = nullptr; cudaGetSymbolAddress((void**)&pWh2,  g_Wh2);
    float* ps2s  = nullptr; cudaGetSymbolAddress((void**)&ps2s,  g_s2src);
    float* ps2d  = nullptr; cudaGetSymbolAddress((void**)&ps2d,  g_s2dst);

    const int attn_smem = (2*513*9 + 2*512 + 2*512) * 4 + 512 * 4;   // 47176 B
    cudaFuncSetAttribute(k_attn<0>, cudaFuncAttributeMaxDynamicSharedMemorySize, attn_smem);
    cudaFuncSetAttribute(k_attn<1>, cudaFuncAttributeMaxDynamicSharedMemorySize, attn_smem);
    cudaFuncSetAttribute(k_fc1,     cudaFuncAttributeMaxDynamicSharedMemorySize, 512*36*4);
    cudaFuncSetAttribute((const void*)k_gemm<1, true >, cudaFuncAttributeMaxDynamicSharedMemorySize, SMEM_GEMM);
    cudaFuncSetAttribute((const void*)k_gemm<8, false>, cudaFuncAttributeMaxDynamicSharedMemorySize, SMEM_GEMM);

    k_gemm<1, true ><<<dim3(256, 8), 256, SMEM_GEMM>>>(state, 64, W_heads, a_src, a_dst,
                                                       pWh, pss, psd);
    k_sort<0><<<BHv, 512>>>();
    k_attn<0><<<dim3(BHv, 8), 512, attn_smem>>>();
    k_gemm<8, false><<<256, 256, SMEM_GEMM>>>(px, 512, W_out, a_out_src, a_out_dst,
                                              pWh2, ps2s, ps2d);
    k_sort<1><<<Bv, 512>>>();
    k_attn<1><<<dim3(Bv, 8), 512, attn_smem>>>();
    k_fc1<<<dim3(64, 4), 256, 512*36*4>>>(fc1_w);
    k_fc1r<<<32, 256>>>(fc1_b);
    k_fc2<<<32, 256>>>(fc2_w, fc2_b);
    k_fc3<<<32, 128>>>(fc3_w, fc3_b, out);
}

// round 12
// speedup vs baseline: 1.0022x; 1.0022x over previous
#include <cuda_runtime.h>
#include <cuda_bf16.h>
#include <cstdint>

#define Bv 32
#define Nv 512
#define Hv 8
#define BHv 256

// ---------------- scratch ----------------
__device__ float g_Wh   [(size_t)BHv*Nv*64];
__device__ float g_ssrc [BHv*Nv];
__device__ float g_sdst [BHv*Nv];
__device__ int   g_perm1[BHv*Nv];
__device__ float g_B1a  [BHv*Nv];
__device__ float g_B2a  [BHv*Nv];
__device__ int   g_k1   [BHv*Nv];
__device__ float g_A1a  [BHv*Nv];
__device__ float g_A2a  [BHv*Nv];
__device__ float g_inv1 [BHv*Nv];

__device__ float g_x    [(size_t)Bv*Nv*512];
__device__ float g_Wh2  [(size_t)Bv*Nv*64];
__device__ float g_s2src[Bv*Nv];
__device__ float g_s2dst[Bv*Nv];
__device__ int   g_perm2[Bv*Nv];
__device__ float g_B1b  [Bv*Nv];
__device__ float g_B2b  [Bv*Nv];
__device__ int   g_k2   [Bv*Nv];
__device__ float g_A1b  [Bv*Nv];
__device__ float g_A2b  [Bv*Nv];
__device__ float g_inv2 [Bv*Nv];

__device__ float g_z    [(size_t)Bv*Nv*64];
__device__ float g_part [(size_t)256*32*256];
__device__ float g_z2   [32*256];
__device__ float g_z3   [32*256];

// =====================================================================
// Split-bf16 tensor-core GEMM, 64-row tiles, register-prefetch pipeline.
// C[64,64] tile = A[64,K] @ W[K,64];  3x mma: AhWh + AlWh + AhWl.
// Warps: (wid&3) -> 16-row band, (wid>>2) -> 32-col half.
// Fused row reductions s1 = C@av, s2 = C@bv (cross-warp smem reduce).
// =====================================================================
__device__ __forceinline__ void mma_bf16(float c[4],
        unsigned a0, unsigned a1, unsigned a2, unsigned a3,
        unsigned b0, unsigned b1) {
    asm volatile(
        "mma.sync.aligned.m16n8k16.row.col.f32.bf16.bf16.f32 "
        "{%0,%1,%2,%3}, {%4,%5,%6,%7}, {%8,%9}, {%0,%1,%2,%3};\n"
        : "+f"(c[0]), "+f"(c[1]), "+f"(c[2]), "+f"(c[3])
        : "r"(a0), "r"(a1), "r"(a2), "r"(a3), "r"(b0), "r"(b1));
}

#define SMEM_GEMM ((2*64*72 + 2*64*72) * 2)   // 36864 bytes

template<int NCH, bool HEADS>
__global__ __launch_bounds__(256) void k_gemm(const float* __restrict__ A, int lda,
                       const float* __restrict__ W,
                       const float* __restrict__ av, const float* __restrict__ bvv,
                       float* __restrict__ outC,
                       float* __restrict__ s1, float* __restrict__ s2) {
    extern __shared__ __align__(16) unsigned char smem_raw[];
    __nv_bfloat16* Ah  = (__nv_bfloat16*)smem_raw;     // [64][72]
    __nv_bfloat16* Al  = Ah  + 64*72;
    __nv_bfloat16* Whs = Al  + 64*72;                  // [64][72] transposed [o][f]
    __nv_bfloat16* Wls = Whs + 64*72;
    __shared__ float sred[2][2][64];

    int tid = threadIdx.x;
    int row0 = blockIdx.x * 64;
    int h = HEADS ? blockIdx.y : 0;
    const float* Wbase = HEADS ? (W + h*4096) : W;
    const float* avp = HEADS ? (av + h*64) : av;
    const float* bvp = HEADS ? (bvv + h*64) : bvv;
    size_t base_out = HEADS ? ((size_t)(row0 >> 9)*4096 + (size_t)h*512 + (row0 & 511))
                            : (size_t)row0;

    int lane = tid & 31, wid = tid >> 5;
    int g = lane >> 2, t = lane & 3;
    int mw = (wid & 3) * 16;      // row band
    int nh = (wid >> 2) * 32;     // col half

    float acc[4][4];
    #pragma unroll
    for (int nt = 0; nt < 4; ++nt)
        #pragma unroll
        for (int j = 0; j < 4; ++j) acc[nt][j] = 0.f;

    int ldf4 = lda >> 2;
    const float4* Abase = (const float4*)(A + (size_t)row0 * lda);

    float4 ra[4];
    float  rwv[16];
    // prefetch chunk 0
    #pragma unroll
    for (int p = 0; p < 4; ++p) {
        int i = tid + p*256;
        ra[p] = Abase[(size_t)(i >> 4) * ldf4 + (i & 15)];
    }
    #pragma unroll
    for (int p = 0; p < 16; ++p) rwv[p] = Wbase[tid + p*256];

    for (int ch = 0; ch < NCH; ++ch) {
        __syncthreads();      // previous mma done; smem free
        // convert + store staged regs
        #pragma unroll
        for (int p = 0; p < 4; ++p) {
            int i = tid + p*256;
            int r = i >> 4, c4 = i & 15;
            float4 v = ra[p];
            __nv_bfloat16 h0 = __float2bfloat16_rn(v.x);
            __nv_bfloat16 h1 = __float2bfloat16_rn(v.y);
            __nv_bfloat16 h2 = __float2bfloat16_rn(v.z);
            __nv_bfloat16 h3 = __float2bfloat16_rn(v.w);
            __nv_bfloat16 l0 = __float2bfloat16_rn(v.x - __bfloat162float(h0));
            __nv_bfloat16 l1 = __float2bfloat16_rn(v.y - __bfloat162float(h1));
            __nv_bfloat16 l2 = __float2bfloat16_rn(v.z - __bfloat162float(h2));
            __nv_bfloat16 l3 = __float2bfloat16_rn(v.w - __bfloat162float(h3));
            int base = r*72 + c4*4;
            __nv_bfloat162 hh0; hh0.x = h0; hh0.y = h1;
            __nv_bfloat162 hh1; hh1.x = h2; hh1.y = h3;
            __nv_bfloat162 ll0; ll0.x = l0; ll0.y = l1;
            __nv_bfloat162 ll1; ll1.x = l2; ll1.y = l3;
            *(__nv_bfloat162*)&Ah[base]     = hh0;
            *(__nv_bfloat162*)&Ah[base + 2] = hh1;
            *(__nv_bfloat162*)&Al[base]     = ll0;
            *(__nv_bfloat162*)&Al[base + 2] = ll1;
        }
        #pragma unroll
        for (int p = 0; p < 16; ++p) {
            int i = tid + p*256;
            int f = i >> 6, o = i & 63;
            float v = rwv[p];
            __nv_bfloat16 hi = __float2bfloat16_rn(v);
            Whs[o*72 + f] = hi;
            Wls[o*72 + f] = __float2bfloat16_rn(v - __bfloat162float(hi));
        }
        __syncthreads();
        // prefetch next chunk (overlaps with mma below)
        if (ch + 1 < NCH) {
            #pragma unroll
            for (int p = 0; p < 4; ++p) {
                int i = tid + p*256;
                ra[p] = Abase[(size_t)(i >> 4) * ldf4 + (ch+1)*16 + (i & 15)];
            }
            #pragma unroll
            for (int p = 0; p < 16; ++p) rwv[p] = Wbase[(ch+1)*4096 + tid + p*256];
        }
        // mma on staged chunk
        #pragma unroll
        for (int ks = 0; ks < 4; ++ks) {
            int ka = ks*16 + t*2;
            unsigned ah0 = *(const unsigned*)&Ah[(mw+g  )*72 + ka];
            unsigned ah1 = *(const unsigned*)&Ah[(mw+g+8)*72 + ka];
            unsigned ah2 = *(const unsigned*)&Ah[(mw+g  )*72 + ka + 8];
            unsigned ah3 = *(const unsigned*)&Ah[(mw+g+8)*72 + ka + 8];
            unsigned al0 = *(const unsigned*)&Al[(mw+g  )*72 + ka];
            unsigned al1 = *(const unsigned*)&Al[(mw+g+8)*72 + ka];
            unsigned al2 = *(const unsigned*)&Al[(mw+g  )*72 + ka + 8];
            unsigned al3 = *(const unsigned*)&Al[(mw+g+8)*72 + ka + 8];
            #pragma unroll
            for (int nt = 0; nt < 4; ++nt) {
                int ob = nh + nt*8 + g;
                unsigned bh0 = *(const unsigned*)&Whs[ob*72 + ka];
                unsigned bh1 = *(const unsigned*)&Whs[ob*72 + ka + 8];
                unsigned bl0 = *(const unsigned*)&Wls[ob*72 + ka];
                unsigned bl1 = *(const unsigned*)&Wls[ob*72 + ka + 8];
                mma_bf16(acc[nt], ah0, ah1, ah2, ah3, bh0, bh1);
                mma_bf16(acc[nt], al0, al1, al2, al3, bh0, bh1);
                mma_bf16(acc[nt], ah0, ah1, ah2, ah3, bl0, bl1);
            }
        }
    }

    // epilogue: store C + fused row reductions
    size_t rA = base_out + mw + g;
    size_t rB = rA + 8;
    float p1A = 0.f, p2A = 0.f, p1B = 0.f, p2B = 0.f;
    #pragma unroll
    for (int nt = 0; nt < 4; ++nt) {
        int col = nh + nt*8 + t*2;
        float a0 = avp[col], a1 = avp[col+1];
        float b0 = bvp[col], b1 = bvp[col+1];
        *(float2*)&outC[rA*64 + col] = make_float2(acc[nt][0], acc[nt][1]);
        *(float2*)&outC[rB*64 + col] = make_float2(acc[nt][2], acc[nt][3]);
        p1A += acc[nt][0]*a0 + acc[nt][1]*a1;
        p2A += acc[nt][0]*b0 + acc[nt][1]*b1;
        p1B += acc[nt][2]*a0 + acc[nt][3]*a1;
        p2B += acc[nt][2]*b0 + acc[nt][3]*b1;
    }
    #pragma unroll
    for (int d = 1; d <= 2; d <<= 1) {
        p1A += __shfl_xor_sync(0xffffffffu, p1A, d);
        p2A += __shfl_xor_sync(0xffffffffu, p2A, d);
        p1B += __shfl_xor_sync(0xffffffffu, p1B, d);
        p2B += __shfl_xor_sync(0xffffffffu, p2B, d);
    }
    int nhi = wid >> 2;
    if (t == 0) {
        sred[0][nhi][mw + g]     = p1A;
        sred[0][nhi][mw + g + 8] = p1B;
        sred[1][nhi][mw + g]     = p2A;
        sred[1][nhi][mw + g + 8] = p2B;
    }
    __syncthreads();
    if (tid < 64) {
        s1[base_out + tid] = sred[0][0][tid] + sred[0][1][tid];
        s2[base_out + tid] = sred[1][0][tid] + sred[1][1][tid];
    }
}

// =====================================================================
// K2 (templated): 64-bit-packed bitonic sort + warp scans + thresholds
// =====================================================================
template <int STAGE>
__global__ void k_sort() {
    const float* ssrc = STAGE ? g_s2src : g_ssrc;
    const float* sdst = STAGE ? g_s2dst : g_sdst;
    int*   perm  = STAGE ? g_perm2 : g_perm1;
    float* B1o   = STAGE ? g_B1b   : g_B1a;
    float* B2o   = STAGE ? g_B2b   : g_B2a;
    int*   kout  = STAGE ? g_k2    : g_k1;
    float* A1o   = STAGE ? g_A1b   : g_A1a;
    float* A2o   = STAGE ? g_A2b   : g_A2a;
    float* invo  = STAGE ? g_inv2  : g_inv1;

    __shared__ unsigned long long sx[512];
    __shared__ float skey[512];
    __shared__ float sD1[513], sD2[513];
    __shared__ float wsum1[16], wsum2[16];

    int bh = blockIdx.x, tid = threadIdx.x, base = bh * 512;
    const unsigned FULL = 0xffffffffu;

    float fv = sdst[base + tid];
    unsigned kb = __float_as_uint(fv);
    kb = (kb & 0x80000000u) ? ~kb : (kb | 0x80000000u);
    unsigned long long v = ((unsigned long long)kb << 32) | (unsigned)tid;

    for (int k = 2; k <= 512; k <<= 1) {
        bool up = ((tid & k) == 0);
        for (int j = k >> 1; j > 0; j >>= 1) {
            unsigned long long w;
            if (j >= 32) {
                sx[tid] = v; __syncthreads();
                w = sx[tid ^ j]; __syncthreads();
            } else {
                w = __shfl_xor_sync(FULL, v, j);
            }
            bool takeMin = (((tid & j) == 0) == up);
            v = takeMin ? (v < w ? v : w) : (v > w ? v : w);
        }
    }
    unsigned kb2 = (unsigned)(v >> 32);
    kb2 = (kb2 & 0x80000000u) ? (kb2 & 0x7fffffffu) : ~kb2;
    float tj = __uint_as_float(kb2);
    int srcidx = (int)(v & 0xffffffffu);
    skey[tid] = tj;
    __syncthreads();
    float maxt = skey[511];

    float b1 = __expf(tj - maxt);
    float b2 = __expf(0.2f * (tj - maxt));
    perm[base + tid] = srcidx;
    B1o[base + tid] = b1; B2o[base + tid] = b2;

    int lane = tid & 31, wid = tid >> 5;
    float s1 = b1, s2 = b2;
    #pragma unroll
    for (int d = 1; d < 32; d <<= 1) {
        float t1 = __shfl_up_sync(FULL, s1, d);
        float t2 = __shfl_up_sync(FULL, s2, d);
        if (lane >= d) { s1 += t1; s2 += t2; }
    }
    if (lane == 31) { wsum1[wid] = s1; wsum2[wid] = s2; }
    __syncthreads();
    if (tid < 16) {
        float a = wsum1[tid], c = wsum2[tid];
        #pragma unroll
        for (int d = 1; d < 16; d <<= 1) {
            float t = __shfl_up_sync(0x0000ffffu, a, d);
            float u = __shfl_up_sync(0x0000ffffu, c, d);
            if (tid >= d) { a += t; c += u; }
        }
        wsum1[tid] = a; wsum2[tid] = c;
    }
    __syncthreads();
    float off1 = wid ? wsum1[wid-1] : 0.f;
    float off2 = wid ? wsum2[wid-1] : 0.f;
    sD1[tid + 1] = s1 + off1;
    sD2[tid + 1] = s2 + off2;
    if (tid == 0) { sD1[0] = 0.f; sD2[0] = 0.f; }
    __syncthreads();

    float D1tot = sD1[512];
    float s = ssrc[base + tid];
    float thr = -s;
    int lo = 0, hi = 512;
    while (lo < hi) { int mid = (lo + hi) >> 1; if (skey[mid] <= thr) lo = mid + 1; else hi = mid; }
    float val = s + maxt;
    float m = val > 0.f ? val : 0.2f * val;
    float a1 = __expf(val - m);
    float a2 = __expf(0.2f * val - m);
    float den = a1 * (D1tot - sD1[lo]) + a2 * sD2[lo];
    kout[base + tid] = lo;
    A1o[base + tid] = a1; A2o[base + tid] = a2;
    invo[base + tid] = 1.f / den;
}

// =====================================================================
// K3 (templated): vector prefix sums + emission, 8-col blocks (~46KB smem)
// grid (nbh, 8) x 512
// =====================================================================
template <int STAGE>
__global__ void k_attn() {
    const float* Wh    = STAGE ? g_Wh2   : g_Wh;
    const int*   perm  = STAGE ? g_perm2 : g_perm1;
    const float* B1    = STAGE ? g_B1b   : g_B1a;
    const float* B2    = STAGE ? g_B2b   : g_B2a;
    const int*   kidx  = STAGE ? g_k2    : g_k1;
    const float* A1    = STAGE ? g_A1b   : g_A1a;
    const float* A2    = STAGE ? g_A2b   : g_A2a;
    const float* invd  = STAGE ? g_inv2  : g_inv1;
    float*       out   = STAGE ? g_z     : g_x;
    const int    Hn    = STAGE ? 1 : 8;
    const int    ld    = STAGE ? 64 : 512;

    extern __shared__ float sm[];
    float* P1  = sm;                   // 513*9
    float* P2  = P1 + 513*9;
    float* Ct1 = P2 + 513*9;           // 64*8
    float* Ct2 = Ct1 + 512;
    float* sB1 = Ct2 + 512;            // 512
    float* sB2 = sB1 + 512;
    int*   sperm = (int*)(sB2 + 512);  // 512

    int bh = blockIdx.x, cb = blockIdx.y;
    int tid = threadIdx.x;
    int base = bh * 512;
    int colbase = cb * 8;
    sB1[tid] = B1[base + tid];
    sB2[tid] = B2[base + tid];
    sperm[tid] = perm[base + tid];
    __syncthreads();

    int o = tid & 7, c = tid >> 3;     // c in [0,64)
    {
        float run1 = 0.f, run2 = 0.f;
        int pos0 = c * 8;
        const float* whb = Wh + (size_t)base * 64 + colbase + o;
        #pragma unroll
        for (int rr = 0; rr < 8; ++rr) {
            int pos = pos0 + rr;
            P1[pos*9 + o] = run1; P2[pos*9 + o] = run2;
            float w = whb[(size_t)sperm[pos] * 64];
            run1 = fmaf(sB1[pos], w, run1);
            run2 = fmaf(sB2[pos], w, run2);
        }
        Ct1[c*8 + o] = run1; Ct2[c*8 + o] = run2;
    }
    __syncthreads();
    {
        float off1 = 0.f, off2 = 0.f, tot1 = 0.f, tot2 = 0.f;
        #pragma unroll 8
        for (int cc = 0; cc < 64; ++cc) {
            float v1 = Ct1[cc*8 + o], v2 = Ct2[cc*8 + o];
            if (cc < c) { off1 += v1; off2 += v2; }
            tot1 += v1; tot2 += v2;
        }
        int pos0 = c * 8;
        #pragma unroll
        for (int rr = 0; rr < 8; ++rr) {
            P1[(pos0+rr)*9 + o] += off1;
            P2[(pos0+rr)*9 + o] += off2;
        }
        if (c == 0) { P1[512*9 + o] = tot1; P2[512*9 + o] = tot2; }
    }
    __syncthreads();
    int b = bh / Hn, h = bh % Hn;
    size_t outbase = (size_t)b * 512 * ld + (size_t)h * 64 + colbase + o;
    float t1 = P1[512*9 + o];
    #pragma unroll
    for (int it = 0; it < 8; ++it) {
        int i = c + it * 64;
        int k = kidx[base + i];
        float a1 = A1[base + i], a2 = A2[base + i], inv = invd[base + i];
        float p1 = P1[k*9 + o], p2 = P2[k*9 + o];
        float valo = (a1 * (t1 - p1) + a2 * p2) * inv;
        if (!STAGE) valo = valo > 0.f ? valo : (__expf(valo) - 1.f);
        out[outbase + (size_t)i * ld] = valo;
    }
}

// =====================================================================
// K5: fc1 partials with transposed z staging (broadcast float4 LDS)
// grid (64 kchunks, 4 colblocks) x 256, 72KB smem
// =====================================================================
__global__ void k_fc1(const float* __restrict__ fc1_w) {
    extern __shared__ float zs[];   // [512][36] transposed: zs[kk*36 + r]
    int kc = blockIdx.x, cb = blockIdx.y;
    int tid = threadIdx.x;
    int c = tid & 63, ks = tid >> 6;
    int k0 = kc * 512;
    for (int i = tid; i < 32*512; i += 256) {
        int rr = i >> 9, kk = i & 511;
        zs[kk*36 + rr] = g_z[(size_t)rr*32768 + k0 + kk];
    }
    __syncthreads();
    float acc[32];
    #pragma unroll
    for (int r = 0; r < 32; ++r) acc[r] = 0.f;
    const float* wp = fc1_w + (size_t)(k0 + ks*128)*256 + cb*64 + c;
    for (int kk = 0; kk < 128; ++kk) {
        float w = wp[(size_t)kk * 256];
        const float* zc = zs + (ks*128 + kk)*36;
        #pragma unroll
        for (int r4 = 0; r4 < 8; ++r4) {
            float4 z4 = *(const float4*)&zc[r4*4];
            acc[r4*4+0] = fmaf(z4.x, w, acc[r4*4+0]);
            acc[r4*4+1] = fmaf(z4.y, w, acc[r4*4+1]);
            acc[r4*4+2] = fmaf(z4.z, w, acc[r4*4+2]);
            acc[r4*4+3] = fmaf(z4.w, w, acc[r4*4+3]);
        }
    }
    int pidx = kc*4 + ks;
    for (int r = 0; r < 32; ++r)
        g_part[((size_t)pidx*32 + r)*256 + cb*64 + c] = acc[r];
}

__global__ void k_fc1r(const float* __restrict__ fc1_b) {
    int r = blockIdx.x; int c = threadIdx.x;
    float s = 0.f;
    for (int p = 0; p < 256; ++p) s += g_part[((size_t)p*32 + r)*256 + c];
    s += fc1_b[c];
    g_z2[r*256 + c] = s > 0.f ? s : 0.f;
}

__global__ void k_fc2(const float* __restrict__ w, const float* __restrict__ bias) {
    __shared__ float zr[256];
    int r = blockIdx.x; int c = threadIdx.x;
    zr[c] = g_z2[r*256 + c];
    __syncthreads();
    float s = bias[c];
    for (int k = 0; k < 256; ++k) s = fmaf(zr[k], w[(size_t)k*256 + c], s);
    g_z3[r*256 + c] = s > 0.f ? s : 0.f;
}

__global__ void k_fc3(const float* __restrict__ w, const float* __restrict__ bias,
                      float* __restrict__ out) {
    int r = blockIdx.x; int tid = threadIdx.x;
    int a = tid >> 5, lane = tid & 31;
    float s = 0.f;
    for (int k = lane; k < 256; k += 32) s = fmaf(g_z3[r*256 + k], w[k*4 + a], s);
    #pragma unroll
    for (int d = 16; d > 0; d >>= 1) s += __shfl_down_sync(0xffffffffu, s, d);
    if (lane == 0) out[r*4 + a] = tanhf(s + bias[a]);
}

// =====================================================================
extern "C" void kernel_launch(void* const* d_in, const int* in_sizes, int n_in,
                              void* d_out, int out_size) {
    const float* state     = (const float*)d_in[0];
    const float* W_heads   = (const float*)d_in[1];
    const float* a_src     = (const float*)d_in[2];
    const float* a_dst     = (const float*)d_in[3];
    const float* W_out     = (const float*)d_in[4];
    const float* a_out_src = (const float*)d_in[5];
    const float* a_out_dst = (const float*)d_in[6];
    const float* fc1_w     = (const float*)d_in[7];
    const float* fc1_b     = (const float*)d_in[8];
    const float* fc2_w     = (const float*)d_in[9];
    const float* fc2_b     = (const float*)d_in[10];
    const float* fc3_w     = (const float*)d_in[11];
    const float* fc3_b     = (const float*)d_in[12];
    float* out = (float*)d_out;

    float* pWh   = nullptr; cudaGetSymbolAddress((void**)&pWh,   g_Wh);
    float* pss   = nullptr; cudaGetSymbolAddress((void**)&pss,   g_ssrc);
    float* psd   = nullptr; cudaGetSymbolAddress((void**)&psd,   g_sdst);
    float* px    = nullptr; cudaGetSymbolAddress((void**)&px,    g_x);
    float* pWh2  = nullptr; cudaGetSymbolAddress((void**)&pWh2,  g_Wh2);
    float* ps2s  = nullptr; cudaGetSymbolAddress((void**)&ps2s,  g_s2src);
    float* ps2d  = nullptr; cudaGetSymbolAddress((void**)&ps2d,  g_s2dst);

    const int attn_smem = (2*513*9 + 2*512 + 2*512) * 4 + 512 * 4;   // 47176 B
    cudaFuncSetAttribute(k_attn<0>, cudaFuncAttributeMaxDynamicSharedMemorySize, attn_smem);
    cudaFuncSetAttribute(k_attn<1>, cudaFuncAttributeMaxDynamicSharedMemorySize, attn_smem);
    cudaFuncSetAttribute(k_fc1,     cudaFuncAttributeMaxDynamicSharedMemorySize, 512*36*4);
    cudaFuncSetAttribute((const void*)k_gemm<1, true >, cudaFuncAttributeMaxDynamicSharedMemorySize, SMEM_GEMM);
    cudaFuncSetAttribute((const void*)k_gemm<8, false>, cudaFuncAttributeMaxDynamicSharedMemorySize, SMEM_GEMM);

    k_gemm<1, true ><<<dim3(256, 8), 256, SMEM_GEMM>>>(state, 64, W_heads, a_src, a_dst,
                                                       pWh, pss, psd);
    k_sort<0><<<BHv, 512>>>();
    k_attn<0><<<dim3(BHv, 8), 512, attn_smem>>>();
    k_gemm<8, false><<<256, 256, SMEM_GEMM>>>(px, 512, W_out, a_out_src, a_out_dst,
                                              pWh2, ps2s, ps2d);
    k_sort<1><<<Bv, 512>>>();
    k_attn<1><<<dim3(Bv, 8), 512, attn_smem>>>();
    k_fc1<<<dim3(64, 4), 256, 512*36*4>>>(fc1_w);
    k_fc1r<<<32, 256>>>(fc1_b);
    k_fc2<<<32, 256>>>(fc2_w, fc2_b);
    k_fc3<<<32, 128>>>(fc3_w, fc3_b, out);
}

// round 13
// speedup vs baseline: 1.0215x; 1.0193x over previous
#include <cuda_runtime.h>
#include <cuda_bf16.h>
#include <cstdint>

#define Bv 32
#define Nv 512
#define Hv 8
#define BHv 256

// ---------------- scratch ----------------
__device__ float g_Wh   [(size_t)BHv*Nv*64];
__device__ float g_ssrc [BHv*Nv];
__device__ float g_sdst [BHv*Nv];
__device__ int   g_perm1[BHv*Nv];
__device__ float g_B1a  [BHv*Nv];
__device__ float g_B2a  [BHv*Nv];
__device__ int   g_k1   [BHv*Nv];
__device__ float g_A1a  [BHv*Nv];
__device__ float g_A2a  [BHv*Nv];
__device__ float g_inv1 [BHv*Nv];

__device__ float g_x    [(size_t)Bv*Nv*512];
__device__ float g_Wh2  [(size_t)Bv*Nv*64];
__device__ float g_s2src[Bv*Nv];
__device__ float g_s2dst[Bv*Nv];
__device__ int   g_perm2[Bv*Nv];
__device__ float g_B1b  [Bv*Nv];
__device__ float g_B2b  [Bv*Nv];
__device__ int   g_k2   [Bv*Nv];
__device__ float g_A1b  [Bv*Nv];
__device__ float g_A2b  [Bv*Nv];
__device__ float g_inv2 [Bv*Nv];

__device__ float g_z    [(size_t)Bv*Nv*64];
__device__ float g_part [(size_t)256*32*256];
__device__ float g_z2   [32*256];
__device__ float g_z3   [32*256];

// =====================================================================
// Split-bf16 tensor-core GEMM, 64-row tiles, register-prefetch pipeline.
// C[64,64] tile = A[64,K] @ W[K,64];  3x mma: AhWh + AlWh + AhWl.
// Warps: (wid&3) -> 16-row band, (wid>>2) -> 32-col half.
// Fused row reductions s1 = C@av, s2 = C@bv (cross-warp smem reduce).
// =====================================================================
__device__ __forceinline__ void mma_bf16(float c[4],
        unsigned a0, unsigned a1, unsigned a2, unsigned a3,
        unsigned b0, unsigned b1) {
    asm volatile(
        "mma.sync.aligned.m16n8k16.row.col.f32.bf16.bf16.f32 "
        "{%0,%1,%2,%3}, {%4,%5,%6,%7}, {%8,%9}, {%0,%1,%2,%3};\n"
        : "+f"(c[0]), "+f"(c[1]), "+f"(c[2]), "+f"(c[3])
        : "r"(a0), "r"(a1), "r"(a2), "r"(a3), "r"(b0), "r"(b1));
}

#define SMEM_GEMM ((2*64*72 + 2*64*72) * 2)   // 36864 bytes

template<int NCH, bool HEADS>
__global__ __launch_bounds__(256) void k_gemm(const float* __restrict__ A, int lda,
                       const float* __restrict__ W,
                       const float* __restrict__ av, const float* __restrict__ bvv,
                       float* __restrict__ outC,
                       float* __restrict__ s1, float* __restrict__ s2) {
    extern __shared__ __align__(16) unsigned char smem_raw[];
    __nv_bfloat16* Ah  = (__nv_bfloat16*)smem_raw;     // [64][72]
    __nv_bfloat16* Al  = Ah  + 64*72;
    __nv_bfloat16* Whs = Al  + 64*72;                  // [64][72] transposed [o][f]
    __nv_bfloat16* Wls = Whs + 64*72;
    __shared__ float sred[2][2][64];

    int tid = threadIdx.x;
    int row0 = blockIdx.x * 64;
    int h = HEADS ? blockIdx.y : 0;
    const float* Wbase = HEADS ? (W + h*4096) : W;
    const float* avp = HEADS ? (av + h*64) : av;
    const float* bvp = HEADS ? (bvv + h*64) : bvv;
    size_t base_out = HEADS ? ((size_t)(row0 >> 9)*4096 + (size_t)h*512 + (row0 & 511))
                            : (size_t)row0;

    int lane = tid & 31, wid = tid >> 5;
    int g = lane >> 2, t = lane & 3;
    int mw = (wid & 3) * 16;      // row band
    int nh = (wid >> 2) * 32;     // col half

    float acc[4][4];
    #pragma unroll
    for (int nt = 0; nt < 4; ++nt)
        #pragma unroll
        for (int j = 0; j < 4; ++j) acc[nt][j] = 0.f;

    int ldf4 = lda >> 2;
    const float4* Abase = (const float4*)(A + (size_t)row0 * lda);

    float4 ra[4];
    float  rwv[16];
    // prefetch chunk 0
    #pragma unroll
    for (int p = 0; p < 4; ++p) {
        int i = tid + p*256;
        ra[p] = Abase[(size_t)(i >> 4) * ldf4 + (i & 15)];
    }
    #pragma unroll
    for (int p = 0; p < 16; ++p) rwv[p] = Wbase[tid + p*256];

    for (int ch = 0; ch < NCH; ++ch) {
        __syncthreads();      // previous mma done; smem free
        // convert + store staged regs
        #pragma unroll
        for (int p = 0; p < 4; ++p) {
            int i = tid + p*256;
            int r = i >> 4, c4 = i & 15;
            float4 v = ra[p];
            __nv_bfloat16 h0 = __float2bfloat16_rn(v.x);
            __nv_bfloat16 h1 = __float2bfloat16_rn(v.y);
            __nv_bfloat16 h2 = __float2bfloat16_rn(v.z);
            __nv_bfloat16 h3 = __float2bfloat16_rn(v.w);
            __nv_bfloat16 l0 = __float2bfloat16_rn(v.x - __bfloat162float(h0));
            __nv_bfloat16 l1 = __float2bfloat16_rn(v.y - __bfloat162float(h1));
            __nv_bfloat16 l2 = __float2bfloat16_rn(v.z - __bfloat162float(h2));
            __nv_bfloat16 l3 = __float2bfloat16_rn(v.w - __bfloat162float(h3));
            int base = r*72 + c4*4;
            __nv_bfloat162 hh0; hh0.x = h0; hh0.y = h1;
            __nv_bfloat162 hh1; hh1.x = h2; hh1.y = h3;
            __nv_bfloat162 ll0; ll0.x = l0; ll0.y = l1;
            __nv_bfloat162 ll1; ll1.x = l2; ll1.y = l3;
            *(__nv_bfloat162*)&Ah[base]     = hh0;
            *(__nv_bfloat162*)&Ah[base + 2] = hh1;
            *(__nv_bfloat162*)&Al[base]     = ll0;
            *(__nv_bfloat162*)&Al[base + 2] = ll1;
        }
        #pragma unroll
        for (int p = 0; p < 16; ++p) {
            int i = tid + p*256;
            int f = i >> 6, o = i & 63;
            float v = rwv[p];
            __nv_bfloat16 hi = __float2bfloat16_rn(v);
            Whs[o*72 + f] = hi;
            Wls[o*72 + f] = __float2bfloat16_rn(v - __bfloat162float(hi));
        }
        __syncthreads();
        // prefetch next chunk (overlaps with mma below)
        if (ch + 1 < NCH) {
            #pragma unroll
            for (int p = 0; p < 4; ++p) {
                int i = tid + p*256;
                ra[p] = Abase[(size_t)(i >> 4) * ldf4 + (ch+1)*16 + (i & 15)];
            }
            #pragma unroll
            for (int p = 0; p < 16; ++p) rwv[p] = Wbase[(ch+1)*4096 + tid + p*256];
        }
        // mma on staged chunk
        #pragma unroll
        for (int ks = 0; ks < 4; ++ks) {
            int ka = ks*16 + t*2;
            unsigned ah0 = *(const unsigned*)&Ah[(mw+g  )*72 + ka];
            unsigned ah1 = *(const unsigned*)&Ah[(mw+g+8)*72 + ka];
            unsigned ah2 = *(const unsigned*)&Ah[(mw+g  )*72 + ka + 8];
            unsigned ah3 = *(const unsigned*)&Ah[(mw+g+8)*72 + ka + 8];
            unsigned al0 = *(const unsigned*)&Al[(mw+g  )*72 + ka];
            unsigned al1 = *(const unsigned*)&Al[(mw+g+8)*72 + ka];
            unsigned al2 = *(const unsigned*)&Al[(mw+g  )*72 + ka + 8];
            unsigned al3 = *(const unsigned*)&Al[(mw+g+8)*72 + ka + 8];
            #pragma unroll
            for (int nt = 0; nt < 4; ++nt) {
                int ob = nh + nt*8 + g;
                unsigned bh0 = *(const unsigned*)&Whs[ob*72 + ka];
                unsigned bh1 = *(const unsigned*)&Whs[ob*72 + ka + 8];
                unsigned bl0 = *(const unsigned*)&Wls[ob*72 + ka];
                unsigned bl1 = *(const unsigned*)&Wls[ob*72 + ka + 8];
                mma_bf16(acc[nt], ah0, ah1, ah2, ah3, bh0, bh1);
                mma_bf16(acc[nt], al0, al1, al2, al3, bh0, bh1);
                mma_bf16(acc[nt], ah0, ah1, ah2, ah3, bl0, bl1);
            }
        }
    }

    // epilogue: store C + fused row reductions
    size_t rA = base_out + mw + g;
    size_t rB = rA + 8;
    float p1A = 0.f, p2A = 0.f, p1B = 0.f, p2B = 0.f;
    #pragma unroll
    for (int nt = 0; nt < 4; ++nt) {
        int col = nh + nt*8 + t*2;
        float a0 = avp[col], a1 = avp[col+1];
        float b0 = bvp[col], b1 = bvp[col+1];
        *(float2*)&outC[rA*64 + col] = make_float2(acc[nt][0], acc[nt][1]);
        *(float2*)&outC[rB*64 + col] = make_float2(acc[nt][2], acc[nt][3]);
        p1A += acc[nt][0]*a0 + acc[nt][1]*a1;
        p2A += acc[nt][0]*b0 + acc[nt][1]*b1;
        p1B += acc[nt][2]*a0 + acc[nt][3]*a1;
        p2B += acc[nt][2]*b0 + acc[nt][3]*b1;
    }
    #pragma unroll
    for (int d = 1; d <= 2; d <<= 1) {
        p1A += __shfl_xor_sync(0xffffffffu, p1A, d);
        p2A += __shfl_xor_sync(0xffffffffu, p2A, d);
        p1B += __shfl_xor_sync(0xffffffffu, p1B, d);
        p2B += __shfl_xor_sync(0xffffffffu, p2B, d);
    }
    int nhi = wid >> 2;
    if (t == 0) {
        sred[0][nhi][mw + g]     = p1A;
        sred[0][nhi][mw + g + 8] = p1B;
        sred[1][nhi][mw + g]     = p2A;
        sred[1][nhi][mw + g + 8] = p2B;
    }
    __syncthreads();
    if (tid < 64) {
        s1[base_out + tid] = sred[0][0][tid] + sred[0][1][tid];
        s2[base_out + tid] = sred[1][0][tid] + sred[1][1][tid];
    }
}

// =====================================================================
// K2 (templated): 64-bit-packed bitonic sort + warp scans + thresholds
// =====================================================================
template <int STAGE>
__global__ void k_sort() {
    const float* ssrc = STAGE ? g_s2src : g_ssrc;
    const float* sdst = STAGE ? g_s2dst : g_sdst;
    int*   perm  = STAGE ? g_perm2 : g_perm1;
    float* B1o   = STAGE ? g_B1b   : g_B1a;
    float* B2o   = STAGE ? g_B2b   : g_B2a;
    int*   kout  = STAGE ? g_k2    : g_k1;
    float* A1o   = STAGE ? g_A1b   : g_A1a;
    float* A2o   = STAGE ? g_A2b   : g_A2a;
    float* invo  = STAGE ? g_inv2  : g_inv1;

    __shared__ unsigned long long sx[512];
    __shared__ float skey[512];
    __shared__ float sD1[513], sD2[513];
    __shared__ float wsum1[16], wsum2[16];

    int bh = blockIdx.x, tid = threadIdx.x, base = bh * 512;
    const unsigned FULL = 0xffffffffu;

    float fv = sdst[base + tid];
    unsigned kb = __float_as_uint(fv);
    kb = (kb & 0x80000000u) ? ~kb : (kb | 0x80000000u);
    unsigned long long v = ((unsigned long long)kb << 32) | (unsigned)tid;

    for (int k = 2; k <= 512; k <<= 1) {
        bool up = ((tid & k) == 0);
        for (int j = k >> 1; j > 0; j >>= 1) {
            unsigned long long w;
            if (j >= 32) {
                sx[tid] = v; __syncthreads();
                w = sx[tid ^ j]; __syncthreads();
            } else {
                w = __shfl_xor_sync(FULL, v, j);
            }
            bool takeMin = (((tid & j) == 0) == up);
            v = takeMin ? (v < w ? v : w) : (v > w ? v : w);
        }
    }
    unsigned kb2 = (unsigned)(v >> 32);
    kb2 = (kb2 & 0x80000000u) ? (kb2 & 0x7fffffffu) : ~kb2;
    float tj = __uint_as_float(kb2);
    int srcidx = (int)(v & 0xffffffffu);
    skey[tid] = tj;
    __syncthreads();
    float maxt = skey[511];

    float b1 = __expf(tj - maxt);
    float b2 = __expf(0.2f * (tj - maxt));
    perm[base + tid] = srcidx;
    B1o[base + tid] = b1; B2o[base + tid] = b2;

    int lane = tid & 31, wid = tid >> 5;
    float s1 = b1, s2 = b2;
    #pragma unroll
    for (int d = 1; d < 32; d <<= 1) {
        float t1 = __shfl_up_sync(FULL, s1, d);
        float t2 = __shfl_up_sync(FULL, s2, d);
        if (lane >= d) { s1 += t1; s2 += t2; }
    }
    if (lane == 31) { wsum1[wid] = s1; wsum2[wid] = s2; }
    __syncthreads();
    if (tid < 16) {
        float a = wsum1[tid], c = wsum2[tid];
        #pragma unroll
        for (int d = 1; d < 16; d <<= 1) {
            float t = __shfl_up_sync(0x0000ffffu, a, d);
            float u = __shfl_up_sync(0x0000ffffu, c, d);
            if (tid >= d) { a += t; c += u; }
        }
        wsum1[tid] = a; wsum2[tid] = c;
    }
    __syncthreads();
    float off1 = wid ? wsum1[wid-1] : 0.f;
    float off2 = wid ? wsum2[wid-1] : 0.f;
    sD1[tid + 1] = s1 + off1;
    sD2[tid + 1] = s2 + off2;
    if (tid == 0) { sD1[0] = 0.f; sD2[0] = 0.f; }
    __syncthreads();

    float D1tot = sD1[512];
    float s = ssrc[base + tid];
    float thr = -s;
    int lo = 0, hi = 512;
    while (lo < hi) { int mid = (lo + hi) >> 1; if (skey[mid] <= thr) lo = mid + 1; else hi = mid; }
    float val = s + maxt;
    float m = val > 0.f ? val : 0.2f * val;
    float a1 = __expf(val - m);
    float a2 = __expf(0.2f * val - m);
    float den = a1 * (D1tot - sD1[lo]) + a2 * sD2[lo];
    kout[base + tid] = lo;
    A1o[base + tid] = a1; A2o[base + tid] = a2;
    invo[base + tid] = 1.f / den;
}

// =====================================================================
// K3 (templated): vector prefix sums + emission, 8-col blocks (~46KB smem)
// grid (nbh, 8) x 512
// =====================================================================
template <int STAGE>
__global__ void k_attn() {
    const float* Wh    = STAGE ? g_Wh2   : g_Wh;
    const int*   perm  = STAGE ? g_perm2 : g_perm1;
    const float* B1    = STAGE ? g_B1b   : g_B1a;
    const float* B2    = STAGE ? g_B2b   : g_B2a;
    const int*   kidx  = STAGE ? g_k2    : g_k1;
    const float* A1    = STAGE ? g_A1b   : g_A1a;
    const float* A2    = STAGE ? g_A2b   : g_A2a;
    const float* invd  = STAGE ? g_inv2  : g_inv1;
    float*       out   = STAGE ? g_z     : g_x;
    const int    Hn    = STAGE ? 1 : 8;
    const int    ld    = STAGE ? 64 : 512;

    extern __shared__ float sm[];
    float* P1  = sm;                   // 513*9
    float* P2  = P1 + 513*9;
    float* Ct1 = P2 + 513*9;           // 64*8
    float* Ct2 = Ct1 + 512;
    float* sB1 = Ct2 + 512;            // 512
    float* sB2 = sB1 + 512;
    int*   sperm = (int*)(sB2 + 512);  // 512

    int bh = blockIdx.x, cb = blockIdx.y;
    int tid = threadIdx.x;
    int base = bh * 512;
    int colbase = cb * 8;
    sB1[tid] = B1[base + tid];
    sB2[tid] = B2[base + tid];
    sperm[tid] = perm[base + tid];
    __syncthreads();

    int o = tid & 7, c = tid >> 3;     // c in [0,64)
    {
        float run1 = 0.f, run2 = 0.f;
        int pos0 = c * 8;
        const float* whb = Wh + (size_t)base * 64 + colbase + o;
        #pragma unroll
        for (int rr = 0; rr < 8; ++rr) {
            int pos = pos0 + rr;
            P1[pos*9 + o] = run1; P2[pos*9 + o] = run2;
            float w = whb[(size_t)sperm[pos] * 64];
            run1 = fmaf(sB1[pos], w, run1);
            run2 = fmaf(sB2[pos], w, run2);
        }
        Ct1[c*8 + o] = run1; Ct2[c*8 + o] = run2;
    }
    __syncthreads();
    {
        float off1 = 0.f, off2 = 0.f, tot1 = 0.f, tot2 = 0.f;
        #pragma unroll 8
        for (int cc = 0; cc < 64; ++cc) {
            float v1 = Ct1[cc*8 + o], v2 = Ct2[cc*8 + o];
            if (cc < c) { off1 += v1; off2 += v2; }
            tot1 += v1; tot2 += v2;
        }
        int pos0 = c * 8;
        #pragma unroll
        for (int rr = 0; rr < 8; ++rr) {
            P1[(pos0+rr)*9 + o] += off1;
            P2[(pos0+rr)*9 + o] += off2;
        }
        if (c == 0) { P1[512*9 + o] = tot1; P2[512*9 + o] = tot2; }
    }
    __syncthreads();
    int b = bh / Hn, h = bh % Hn;
    size_t outbase = (size_t)b * 512 * ld + (size_t)h * 64 + colbase + o;
    float t1 = P1[512*9 + o];
    #pragma unroll
    for (int it = 0; it < 8; ++it) {
        int i = c + it * 64;
        int k = kidx[base + i];
        float a1 = A1[base + i], a2 = A2[base + i], inv = invd[base + i];
        float p1 = P1[k*9 + o], p2 = P2[k*9 + o];
        float valo = (a1 * (t1 - p1) + a2 * p2) * inv;
        if (!STAGE) valo = valo > 0.f ? valo : (__expf(valo) - 1.f);
        out[outbase + (size_t)i * ld] = valo;
    }
}

// =====================================================================
// K5: fc1 partials with transposed z staging (broadcast float4 LDS)
// grid (64 kchunks, 4 colblocks) x 256, 72KB smem
// =====================================================================
__global__ void k_fc1(const float* __restrict__ fc1_w) {
    extern __shared__ float zs[];   // [512][36] transposed: zs[kk*36 + r]
    int kc = blockIdx.x, cb = blockIdx.y;
    int tid = threadIdx.x;
    int c = tid & 63, ks = tid >> 6;
    int k0 = kc * 512;
    for (int i = tid; i < 32*512; i += 256) {
        int rr = i >> 9, kk = i & 511;
        zs[kk*36 + rr] = g_z[(size_t)rr*32768 + k0 + kk];
    }
    __syncthreads();
    float acc[32];
    #pragma unroll
    for (int r = 0; r < 32; ++r) acc[r] = 0.f;
    const float* wp = fc1_w + (size_t)(k0 + ks*128)*256 + cb*64 + c;
    for (int kk = 0; kk < 128; ++kk) {
        float w = wp[(size_t)kk * 256];
        const float* zc = zs + (ks*128 + kk)*36;
        #pragma unroll
        for (int r4 = 0; r4 < 8; ++r4) {
            float4 z4 = *(const float4*)&zc[r4*4];
            acc[r4*4+0] = fmaf(z4.x, w, acc[r4*4+0]);
            acc[r4*4+1] = fmaf(z4.y, w, acc[r4*4+1]);
            acc[r4*4+2] = fmaf(z4.z, w, acc[r4*4+2]);
            acc[r4*4+3] = fmaf(z4.w, w, acc[r4*4+3]);
        }
    }
    int pidx = kc*4 + ks;
    for (int r = 0; r < 32; ++r)
        g_part[((size_t)pidx*32 + r)*256 + cb*64 + c] = acc[r];
}

__global__ void k_fc1r(const float* __restrict__ fc1_b) {
    int r = blockIdx.x; int c = threadIdx.x;
    float s = 0.f;
    for (int p = 0; p < 256; ++p) s += g_part[((size_t)p*32 + r)*256 + c];
    s += fc1_b[c];
    g_z2[r*256 + c] = s > 0.f ? s : 0.f;
}

__global__ void k_fc2(const float* __restrict__ w, const float* __restrict__ bias) {
    __shared__ float zr[256];
    int r = blockIdx.x; int c = threadIdx.x;
    zr[c] = g_z2[r*256 + c];
    __syncthreads();
    float s = bias[c];
    for (int k = 0; k < 256; ++k) s = fmaf(zr[k], w[(size_t)k*256 + c], s);
    g_z3[r*256 + c] = s > 0.f ? s : 0.f;
}

__global__ void k_fc3(const float* __restrict__ w, const float* __restrict__ bias,
                      float* __restrict__ out) {
    int r = blockIdx.x; int tid = threadIdx.x;
    int a = tid >> 5, lane = tid & 31;
    float s = 0.f;
    for (int k = lane; k < 256; k += 32) s = fmaf(g_z3[r*256 + k], w[k*4 + a], s);
    #pragma unroll
    for (int d = 16; d > 0; d >>= 1) s += __shfl_down_sync(0xffffffffu, s, d);
    if (lane == 0) out[r*4 + a] = tanhf(s + bias[a]);
}

// =====================================================================
extern "C" void kernel_launch(void* const* d_in, const int* in_sizes, int n_in,
                              void* d_out, int out_size) {
    const float* state     = (const float*)d_in[0];
    const float* W_heads   = (const float*)d_in[1];
    const float* a_src     = (const float*)d_in[2];
    const float* a_dst     = (const float*)d_in[3];
    const float* W_out     = (const float*)d_in[4];
    const float* a_out_src = (const float*)d_in[5];
    const float* a_out_dst = (const float*)d_in[6];
    const float* fc1_w     = (const float*)d_in[7];
    const float* fc1_b     = (const float*)d_in[8];
    const float* fc2_w     = (const float*)d_in[9];
    const float* fc2_b     = (const float*)d_in[10];
    const float* fc3_w     = (const float*)d_in[11];
    const float* fc3_b     = (const float*)d_in[12];
    float* out = (float*)d_out;

    float* pWh   = nullptr; cudaGetSymbolAddress((void**)&pWh,   g_Wh);
    float* pss   = nullptr; cudaGetSymbolAddress((void**)&pss,   g_ssrc);
    float* psd   = nullptr; cudaGetSymbolAddress((void**)&psd,   g_sdst);
    float* px    = nullptr; cudaGetSymbolAddress((void**)&px,    g_x);
    float* pWh2  = nullptr; cudaGetSymbolAddress((void**)&pWh2,  g_Wh2);
    float* ps2s  = nullptr; cudaGetSymbolAddress((void**)&ps2s,  g_s2src);
    float* ps2d  = nullptr; cudaGetSymbolAddress((void**)&ps2d,  g_s2dst);

    const int attn_smem = (2*513*9 + 2*512 + 2*512) * 4 + 512 * 4;   // 47176 B
    cudaFuncSetAttribute(k_attn<0>, cudaFuncAttributeMaxDynamicSharedMemorySize, attn_smem);
    cudaFuncSetAttribute(k_attn<1>, cudaFuncAttributeMaxDynamicSharedMemorySize, attn_smem);
    cudaFuncSetAttribute(k_fc1,     cudaFuncAttributeMaxDynamicSharedMemorySize, 512*36*4);
    cudaFuncSetAttribute((const void*)k_gemm<1, true >, cudaFuncAttributeMaxDynamicSharedMemorySize, SMEM_GEMM);
    cudaFuncSetAttribute((const void*)k_gemm<8, false>, cudaFuncAttributeMaxDynamicSharedMemorySize, SMEM_GEMM);

    k_gemm<1, true ><<<dim3(256, 8), 256, SMEM_GEMM>>>(state, 64, W_heads, a_src, a_dst,
                                                       pWh, pss, psd);
    k_sort<0><<<BHv, 512>>>();
    k_attn<0><<<dim3(BHv, 8), 512, attn_smem>>>();
    k_gemm<8, false><<<256, 256, SMEM_GEMM>>>(px, 512, W_out, a_out_src, a_out_dst,
                                              pWh2, ps2s, ps2d);
    k_sort<1><<<Bv, 512>>>();
    k_attn<1><<<dim3(Bv, 8), 512, attn_smem>>>();
    k_fc1<<<dim3(64, 4), 256, 512*36*4>>>(fc1_w);
    k_fc1r<<<32, 256>>>(fc1_b);
    k_fc2<<<32, 256>>>(fc2_w, fc2_b);
    k_fc3<<<32, 128>>>(fc3_w, fc3_b, out);
}

// round 14
// speedup vs baseline: 1.0219x; 1.0003x over previous
#include <cuda_runtime.h>
#include <cuda_bf16.h>
#include <cstdint>

#define Bv 32
#define Nv 512
#define Hv 8
#define BHv 256

// ---------------- scratch ----------------
__device__ float g_Wh   [(size_t)BHv*Nv*64];
__device__ float g_ssrc [BHv*Nv];
__device__ float g_sdst [BHv*Nv];
__device__ int   g_perm1[BHv*Nv];
__device__ float g_B1a  [BHv*Nv];
__device__ float g_B2a  [BHv*Nv];
__device__ int   g_k1   [BHv*Nv];
__device__ float g_A1a  [BHv*Nv];
__device__ float g_A2a  [BHv*Nv];
__device__ float g_inv1 [BHv*Nv];

__device__ float g_x    [(size_t)Bv*Nv*512];
__device__ float g_Wh2  [(size_t)Bv*Nv*64];
__device__ float g_s2src[Bv*Nv];
__device__ float g_s2dst[Bv*Nv];
__device__ int   g_perm2[Bv*Nv];
__device__ float g_B1b  [Bv*Nv];
__device__ float g_B2b  [Bv*Nv];
__device__ int   g_k2   [Bv*Nv];
__device__ float g_A1b  [Bv*Nv];
__device__ float g_A2b  [Bv*Nv];
__device__ float g_inv2 [Bv*Nv];

__device__ float g_z    [(size_t)Bv*Nv*64];
__device__ float g_part [(size_t)256*32*256];
__device__ float g_z2   [32*256];
__device__ float g_z3   [32*256];

// =====================================================================
// Split-bf16 tensor-core GEMM, 64-row tiles, register-prefetch pipeline.
// C[64,64] tile = A[64,K] @ W[K,64];  3x mma: AhWh + AlWh + AhWl.
// Warps: (wid&3) -> 16-row band, (wid>>2) -> 32-col half.
// Fused row reductions s1 = C@av, s2 = C@bv (cross-warp smem reduce).
// =====================================================================
__device__ __forceinline__ void mma_bf16(float c[4],
        unsigned a0, unsigned a1, unsigned a2, unsigned a3,
        unsigned b0, unsigned b1) {
    asm volatile(
        "mma.sync.aligned.m16n8k16.row.col.f32.bf16.bf16.f32 "
        "{%0,%1,%2,%3}, {%4,%5,%6,%7}, {%8,%9}, {%0,%1,%2,%3};\n"
        : "+f"(c[0]), "+f"(c[1]), "+f"(c[2]), "+f"(c[3])
        : "r"(a0), "r"(a1), "r"(a2), "r"(a3), "r"(b0), "r"(b1));
}

#define SMEM_GEMM ((2*64*72 + 2*64*72) * 2)   // 36864 bytes

template<int NCH, bool HEADS>
__global__ __launch_bounds__(256) void k_gemm(const float* __restrict__ A, int lda,
                       const float* __restrict__ W,
                       const float* __restrict__ av, const float* __restrict__ bvv,
                       float* __restrict__ outC,
                       float* __restrict__ s1, float* __restrict__ s2) {
    extern __shared__ __align__(16) unsigned char smem_raw[];
    __nv_bfloat16* Ah  = (__nv_bfloat16*)smem_raw;     // [64][72]
    __nv_bfloat16* Al  = Ah  + 64*72;
    __nv_bfloat16* Whs = Al  + 64*72;                  // [64][72] transposed [o][f]
    __nv_bfloat16* Wls = Whs + 64*72;
    __shared__ float sred[2][2][64];

    int tid = threadIdx.x;
    int row0 = blockIdx.x * 64;
    int h = HEADS ? blockIdx.y : 0;
    const float* Wbase = HEADS ? (W + h*4096) : W;
    const float* avp = HEADS ? (av + h*64) : av;
    const float* bvp = HEADS ? (bvv + h*64) : bvv;
    size_t base_out = HEADS ? ((size_t)(row0 >> 9)*4096 + (size_t)h*512 + (row0 & 511))
                            : (size_t)row0;

    int lane = tid & 31, wid = tid >> 5;
    int g = lane >> 2, t = lane & 3;
    int mw = (wid & 3) * 16;      // row band
    int nh = (wid >> 2) * 32;     // col half

    float acc[4][4];
    #pragma unroll
    for (int nt = 0; nt < 4; ++nt)
        #pragma unroll
        for (int j = 0; j < 4; ++j) acc[nt][j] = 0.f;

    int ldf4 = lda >> 2;
    const float4* Abase = (const float4*)(A + (size_t)row0 * lda);

    float4 ra[4];
    float  rwv[16];
    // prefetch chunk 0
    #pragma unroll
    for (int p = 0; p < 4; ++p) {
        int i = tid + p*256;
        ra[p] = Abase[(size_t)(i >> 4) * ldf4 + (i & 15)];
    }
    #pragma unroll
    for (int p = 0; p < 16; ++p) rwv[p] = Wbase[tid + p*256];

    for (int ch = 0; ch < NCH; ++ch) {
        __syncthreads();      // previous mma done; smem free
        // convert + store staged regs
        #pragma unroll
        for (int p = 0; p < 4; ++p) {
            int i = tid + p*256;
            int r = i >> 4, c4 = i & 15;
            float4 v = ra[p];
            __nv_bfloat16 h0 = __float2bfloat16_rn(v.x);
            __nv_bfloat16 h1 = __float2bfloat16_rn(v.y);
            __nv_bfloat16 h2 = __float2bfloat16_rn(v.z);
            __nv_bfloat16 h3 = __float2bfloat16_rn(v.w);
            __nv_bfloat16 l0 = __float2bfloat16_rn(v.x - __bfloat162float(h0));
            __nv_bfloat16 l1 = __float2bfloat16_rn(v.y - __bfloat162float(h1));
            __nv_bfloat16 l2 = __float2bfloat16_rn(v.z - __bfloat162float(h2));
            __nv_bfloat16 l3 = __float2bfloat16_rn(v.w - __bfloat162float(h3));
            int base = r*72 + c4*4;
            __nv_bfloat162 hh0; hh0.x = h0; hh0.y = h1;
            __nv_bfloat162 hh1; hh1.x = h2; hh1.y = h3;
            __nv_bfloat162 ll0; ll0.x = l0; ll0.y = l1;
            __nv_bfloat162 ll1; ll1.x = l2; ll1.y = l3;
            *(__nv_bfloat162*)&Ah[base]     = hh0;
            *(__nv_bfloat162*)&Ah[base + 2] = hh1;
            *(__nv_bfloat162*)&Al[base]     = ll0;
            *(__nv_bfloat162*)&Al[base + 2] = ll1;
        }
        #pragma unroll
        for (int p = 0; p < 16; ++p) {
            int i = tid + p*256;
            int f = i >> 6, o = i & 63;
            float v = rwv[p];
            __nv_bfloat16 hi = __float2bfloat16_rn(v);
            Whs[o*72 + f] = hi;
            Wls[o*72 + f] = __float2bfloat16_rn(v - __bfloat162float(hi));
        }
        __syncthreads();
        // prefetch next chunk (overlaps with mma below)
        if (ch + 1 < NCH) {
            #pragma unroll
            for (int p = 0; p < 4; ++p) {
                int i = tid + p*256;
                ra[p] = Abase[(size_t)(i >> 4) * ldf4 + (ch+1)*16 + (i & 15)];
            }
            #pragma unroll
            for (int p = 0; p < 16; ++p) rwv[p] = Wbase[(ch+1)*4096 + tid + p*256];
        }
        // mma on staged chunk
        #pragma unroll
        for (int ks = 0; ks < 4; ++ks) {
            int ka = ks*16 + t*2;
            unsigned ah0 = *(const unsigned*)&Ah[(mw+g  )*72 + ka];
            unsigned ah1 = *(const unsigned*)&Ah[(mw+g+8)*72 + ka];
            unsigned ah2 = *(const unsigned*)&Ah[(mw+g  )*72 + ka + 8];
            unsigned ah3 = *(const unsigned*)&Ah[(mw+g+8)*72 + ka + 8];
            unsigned al0 = *(const unsigned*)&Al[(mw+g  )*72 + ka];
            unsigned al1 = *(const unsigned*)&Al[(mw+g+8)*72 + ka];
            unsigned al2 = *(const unsigned*)&Al[(mw+g  )*72 + ka + 8];
            unsigned al3 = *(const unsigned*)&Al[(mw+g+8)*72 + ka + 8];
            #pragma unroll
            for (int nt = 0; nt < 4; ++nt) {
                int ob = nh + nt*8 + g;
                unsigned bh0 = *(const unsigned*)&Whs[ob*72 + ka];
                unsigned bh1 = *(const unsigned*)&Whs[ob*72 + ka + 8];
                unsigned bl0 = *(const unsigned*)&Wls[ob*72 + ka];
                unsigned bl1 = *(const unsigned*)&Wls[ob*72 + ka + 8];
                mma_bf16(acc[nt], ah0, ah1, ah2, ah3, bh0, bh1);
                mma_bf16(acc[nt], al0, al1, al2, al3, bh0, bh1);
                mma_bf16(acc[nt], ah0, ah1, ah2, ah3, bl0, bl1);
            }
        }
    }

    // epilogue: store C + fused row reductions
    size_t rA = base_out + mw + g;
    size_t rB = rA + 8;
    float p1A = 0.f, p2A = 0.f, p1B = 0.f, p2B = 0.f;
    #pragma unroll
    for (int nt = 0; nt < 4; ++nt) {
        int col = nh + nt*8 + t*2;
        float a0 = avp[col], a1 = avp[col+1];
        float b0 = bvp[col], b1 = bvp[col+1];
        *(float2*)&outC[rA*64 + col] = make_float2(acc[nt][0], acc[nt][1]);
        *(float2*)&outC[rB*64 + col] = make_float2(acc[nt][2], acc[nt][3]);
        p1A += acc[nt][0]*a0 + acc[nt][1]*a1;
        p2A += acc[nt][0]*b0 + acc[nt][1]*b1;
        p1B += acc[nt][2]*a0 + acc[nt][3]*a1;
        p2B += acc[nt][2]*b0 + acc[nt][3]*b1;
    }
    #pragma unroll
    for (int d = 1; d <= 2; d <<= 1) {
        p1A += __shfl_xor_sync(0xffffffffu, p1A, d);
        p2A += __shfl_xor_sync(0xffffffffu, p2A, d);
        p1B += __shfl_xor_sync(0xffffffffu, p1B, d);
        p2B += __shfl_xor_sync(0xffffffffu, p2B, d);
    }
    int nhi = wid >> 2;
    if (t == 0) {
        sred[0][nhi][mw + g]     = p1A;
        sred[0][nhi][mw + g + 8] = p1B;
        sred[1][nhi][mw + g]     = p2A;
        sred[1][nhi][mw + g + 8] = p2B;
    }
    __syncthreads();
    if (tid < 64) {
        s1[base_out + tid] = sred[0][0][tid] + sred[0][1][tid];
        s2[base_out + tid] = sred[1][0][tid] + sred[1][1][tid];
    }
}

// =====================================================================
// K2 (templated): 64-bit-packed bitonic sort + warp scans + thresholds
// =====================================================================
template <int STAGE>
__global__ void k_sort() {
    const float* ssrc = STAGE ? g_s2src : g_ssrc;
    const float* sdst = STAGE ? g_s2dst : g_sdst;
    int*   perm  = STAGE ? g_perm2 : g_perm1;
    float* B1o   = STAGE ? g_B1b   : g_B1a;
    float* B2o   = STAGE ? g_B2b   : g_B2a;
    int*   kout  = STAGE ? g_k2    : g_k1;
    float* A1o   = STAGE ? g_A1b   : g_A1a;
    float* A2o   = STAGE ? g_A2b   : g_A2a;
    float* invo  = STAGE ? g_inv2  : g_inv1;

    __shared__ unsigned long long sx[512];
    __shared__ float skey[512];
    __shared__ float sD1[513], sD2[513];
    __shared__ float wsum1[16], wsum2[16];

    int bh = blockIdx.x, tid = threadIdx.x, base = bh * 512;
    const unsigned FULL = 0xffffffffu;

    float fv = sdst[base + tid];
    unsigned kb = __float_as_uint(fv);
    kb = (kb & 0x80000000u) ? ~kb : (kb | 0x80000000u);
    unsigned long long v = ((unsigned long long)kb << 32) | (unsigned)tid;

    for (int k = 2; k <= 512; k <<= 1) {
        bool up = ((tid & k) == 0);
        for (int j = k >> 1; j > 0; j >>= 1) {
            unsigned long long w;
            if (j >= 32) {
                sx[tid] = v; __syncthreads();
                w = sx[tid ^ j]; __syncthreads();
            } else {
                w = __shfl_xor_sync(FULL, v, j);
            }
            bool takeMin = (((tid & j) == 0) == up);
            v = takeMin ? (v < w ? v : w) : (v > w ? v : w);
        }
    }
    unsigned kb2 = (unsigned)(v >> 32);
    kb2 = (kb2 & 0x80000000u) ? (kb2 & 0x7fffffffu) : ~kb2;
    float tj = __uint_as_float(kb2);
    int srcidx = (int)(v & 0xffffffffu);
    skey[tid] = tj;
    __syncthreads();
    float maxt = skey[511];

    float b1 = __expf(tj - maxt);
    float b2 = __expf(0.2f * (tj - maxt));
    perm[base + tid] = srcidx;
    B1o[base + tid] = b1; B2o[base + tid] = b2;

    int lane = tid & 31, wid = tid >> 5;
    float s1 = b1, s2 = b2;
    #pragma unroll
    for (int d = 1; d < 32; d <<= 1) {
        float t1 = __shfl_up_sync(FULL, s1, d);
        float t2 = __shfl_up_sync(FULL, s2, d);
        if (lane >= d) { s1 += t1; s2 += t2; }
    }
    if (lane == 31) { wsum1[wid] = s1; wsum2[wid] = s2; }
    __syncthreads();
    if (tid < 16) {
        float a = wsum1[tid], c = wsum2[tid];
        #pragma unroll
        for (int d = 1; d < 16; d <<= 1) {
            float t = __shfl_up_sync(0x0000ffffu, a, d);
            float u = __shfl_up_sync(0x0000ffffu, c, d);
            if (tid >= d) { a += t; c += u; }
        }
        wsum1[tid] = a; wsum2[tid] = c;
    }
    __syncthreads();
    float off1 = wid ? wsum1[wid-1] : 0.f;
    float off2 = wid ? wsum2[wid-1] : 0.f;
    sD1[tid + 1] = s1 + off1;
    sD2[tid + 1] = s2 + off2;
    if (tid == 0) { sD1[0] = 0.f; sD2[0] = 0.f; }
    __syncthreads();

    float D1tot = sD1[512];
    float s = ssrc[base + tid];
    float thr = -s;
    int lo = 0, hi = 512;
    while (lo < hi) { int mid = (lo + hi) >> 1; if (skey[mid] <= thr) lo = mid + 1; else hi = mid; }
    float val = s + maxt;
    float m = val > 0.f ? val : 0.2f * val;
    float a1 = __expf(val - m);
    float a2 = __expf(0.2f * val - m);
    float den = a1 * (D1tot - sD1[lo]) + a2 * sD2[lo];
    kout[base + tid] = lo;
    A1o[base + tid] = a1; A2o[base + tid] = a2;
    invo[base + tid] = 1.f / den;
}

// =====================================================================
// K3 (templated): vector prefix sums + emission, 8-col blocks (~46KB smem)
// grid (nbh, 8) x 512
// =====================================================================
template <int STAGE>
__global__ void k_attn() {
    const float* Wh    = STAGE ? g_Wh2   : g_Wh;
    const int*   perm  = STAGE ? g_perm2 : g_perm1;
    const float* B1    = STAGE ? g_B1b   : g_B1a;
    const float* B2    = STAGE ? g_B2b   : g_B2a;
    const int*   kidx  = STAGE ? g_k2    : g_k1;
    const float* A1    = STAGE ? g_A1b   : g_A1a;
    const float* A2    = STAGE ? g_A2b   : g_A2a;
    const float* invd  = STAGE ? g_inv2  : g_inv1;
    float*       out   = STAGE ? g_z     : g_x;
    const int    Hn    = STAGE ? 1 : 8;
    const int    ld    = STAGE ? 64 : 512;

    extern __shared__ float sm[];
    float* P1  = sm;                   // 513*9
    float* P2  = P1 + 513*9;
    float* Ct1 = P2 + 513*9;           // 64*8
    float* Ct2 = Ct1 + 512;
    float* sB1 = Ct2 + 512;            // 512
    float* sB2 = sB1 + 512;
    int*   sperm = (int*)(sB2 + 512);  // 512

    int bh = blockIdx.x, cb = blockIdx.y;
    int tid = threadIdx.x;
    int base = bh * 512;
    int colbase = cb * 8;
    sB1[tid] = B1[base + tid];
    sB2[tid] = B2[base + tid];
    sperm[tid] = perm[base + tid];
    __syncthreads();

    int o = tid & 7, c = tid >> 3;     // c in [0,64)
    {
        float run1 = 0.f, run2 = 0.f;
        int pos0 = c * 8;
        const float* whb = Wh + (size_t)base * 64 + colbase + o;
        #pragma unroll
        for (int rr = 0; rr < 8; ++rr) {
            int pos = pos0 + rr;
            P1[pos*9 + o] = run1; P2[pos*9 + o] = run2;
            float w = whb[(size_t)sperm[pos] * 64];
            run1 = fmaf(sB1[pos], w, run1);
            run2 = fmaf(sB2[pos], w, run2);
        }
        Ct1[c*8 + o] = run1; Ct2[c*8 + o] = run2;
    }
    __syncthreads();
    {
        float off1 = 0.f, off2 = 0.f, tot1 = 0.f, tot2 = 0.f;
        #pragma unroll 8
        for (int cc = 0; cc < 64; ++cc) {
            float v1 = Ct1[cc*8 + o], v2 = Ct2[cc*8 + o];
            if (cc < c) { off1 += v1; off2 += v2; }
            tot1 += v1; tot2 += v2;
        }
        int pos0 = c * 8;
        #pragma unroll
        for (int rr = 0; rr < 8; ++rr) {
            P1[(pos0+rr)*9 + o] += off1;
            P2[(pos0+rr)*9 + o] += off2;
        }
        if (c == 0) { P1[512*9 + o] = tot1; P2[512*9 + o] = tot2; }
    }
    __syncthreads();
    int b = bh / Hn, h = bh % Hn;
    size_t outbase = (size_t)b * 512 * ld + (size_t)h * 64 + colbase + o;
    float t1 = P1[512*9 + o];
    #pragma unroll
    for (int it = 0; it < 8; ++it) {
        int i = c + it * 64;
        int k = kidx[base + i];
        float a1 = A1[base + i], a2 = A2[base + i], inv = invd[base + i];
        float p1 = P1[k*9 + o], p2 = P2[k*9 + o];
        float valo = (a1 * (t1 - p1) + a2 * p2) * inv;
        if (!STAGE) valo = valo > 0.f ? valo : (__expf(valo) - 1.f);
        out[outbase + (size_t)i * ld] = valo;
    }
}

// =====================================================================
// K5: fc1 partials with transposed z staging (broadcast float4 LDS)
// grid (64 kchunks, 4 colblocks) x 256, 72KB smem
// =====================================================================
__global__ void k_fc1(const float* __restrict__ fc1_w) {
    extern __shared__ float zs[];   // [512][36] transposed: zs[kk*36 + r]
    int kc = blockIdx.x, cb = blockIdx.y;
    int tid = threadIdx.x;
    int c = tid & 63, ks = tid >> 6;
    int k0 = kc * 512;
    for (int i = tid; i < 32*512; i += 256) {
        int rr = i >> 9, kk = i & 511;
        zs[kk*36 + rr] = g_z[(size_t)rr*32768 + k0 + kk];
    }
    __syncthreads();
    float acc[32];
    #pragma unroll
    for (int r = 0; r < 32; ++r) acc[r] = 0.f;
    const float* wp = fc1_w + (size_t)(k0 + ks*128)*256 + cb*64 + c;
    for (int kk = 0; kk < 128; ++kk) {
        float w = wp[(size_t)kk * 256];
        const float* zc = zs + (ks*128 + kk)*36;
        #pragma unroll
        for (int r4 = 0; r4 < 8; ++r4) {
            float4 z4 = *(const float4*)&zc[r4*4];
            acc[r4*4+0] = fmaf(z4.x, w, acc[r4*4+0]);
            acc[r4*4+1] = fmaf(z4.y, w, acc[r4*4+1]);
            acc[r4*4+2] = fmaf(z4.z, w, acc[r4*4+2]);
            acc[r4*4+3] = fmaf(z4.w, w, acc[r4*4+3]);
        }
    }
    int pidx = kc*4 + ks;
    for (int r = 0; r < 32; ++r)
        g_part[((size_t)pidx*32 + r)*256 + cb*64 + c] = acc[r];
}

__global__ void k_fc1r(const float* __restrict__ fc1_b) {
    int r = blockIdx.x; int c = threadIdx.x;
    float s = 0.f;
    for (int p = 0; p < 256; ++p) s += g_part[((size_t)p*32 + r)*256 + c];
    s += fc1_b[c];
    g_z2[r*256 + c] = s > 0.f ? s : 0.f;
}

__global__ void k_fc2(const float* __restrict__ w, const float* __restrict__ bias) {
    __shared__ float zr[256];
    int r = blockIdx.x; int c = threadIdx.x;
    zr[c] = g_z2[r*256 + c];
    __syncthreads();
    float s = bias[c];
    for (int k = 0; k < 256; ++k) s = fmaf(zr[k], w[(size_t)k*256 + c], s);
    g_z3[r*256 + c] = s > 0.f ? s : 0.f;
}

__global__ void k_fc3(const float* __restrict__ w, const float* __restrict__ bias,
                      float* __restrict__ out) {
    int r = blockIdx.x; int tid = threadIdx.x;
    int a = tid >> 5, lane = tid & 31;
    float s = 0.f;
    for (int k = lane; k < 256; k += 32) s = fmaf(g_z3[r*256 + k], w[k*4 + a], s);
    #pragma unroll
    for (int d = 16; d > 0; d >>= 1) s += __shfl_down_sync(0xffffffffu, s, d);
    if (lane == 0) out[r*4 + a] = tanhf(s + bias[a]);
}

// =====================================================================
extern "C" void kernel_launch(void* const* d_in, const int* in_sizes, int n_in,
                              void* d_out, int out_size) {
    const float* state     = (const float*)d_in[0];
    const float* W_heads   = (const float*)d_in[1];
    const float* a_src     = (const float*)d_in[2];
    const float* a_dst     = (const float*)d_in[3];
    const float* W_out     = (const float*)d_in[4];
    const float* a_out_src = (const float*)d_in[5];
    const float* a_out_dst = (const float*)d_in[6];
    const float* fc1_w     = (const float*)d_in[7];
    const float* fc1_b     = (const float*)d_in[8];
    const float* fc2_w     = (const float*)d_in[9];
    const float* fc2_b     = (const float*)d_in[10];
    const float* fc3_w     = (const float*)d_in[11];
    const float* fc3_b     = (const float*)d_in[12];
    float* out = (float*)d_out;

    float* pWh   = nullptr; cudaGetSymbolAddress((void**)&pWh,   g_Wh);
    float* pss   = nullptr; cudaGetSymbolAddress((void**)&pss,   g_ssrc);
    float* psd   = nullptr; cudaGetSymbolAddress((void**)&psd,   g_sdst);
    float* px    = nullptr; cudaGetSymbolAddress((void**)&px,    g_x);
    float* pWh2  = nullptr; cudaGetSymbolAddress((void**)&pWh2,  g_Wh2);
    float* ps2s  = nullptr; cudaGetSymbolAddress((void**)&ps2s,  g_s2src);
    float* ps2d  = nullptr; cudaGetSymbolAddress((void**)&ps2d,  g_s2dst);

    const int attn_smem = (2*513*9 + 2*512 + 2*512) * 4 + 512 * 4;   // 47176 B
    cudaFuncSetAttribute(k_attn<0>, cudaFuncAttributeMaxDynamicSharedMemorySize, attn_smem);
    cudaFuncSetAttribute(k_attn<1>, cudaFuncAttributeMaxDynamicSharedMemorySize, attn_smem);
    cudaFuncSetAttribute(k_fc1,     cudaFuncAttributeMaxDynamicSharedMemorySize, 512*36*4);
    cudaFuncSetAttribute((const void*)k_gemm<1, true >, cudaFuncAttributeMaxDynamicSharedMemorySize, SMEM_GEMM);
    cudaFuncSetAttribute((const void*)k_gemm<8, false>, cudaFuncAttributeMaxDynamicSharedMemorySize, SMEM_GEMM);

    k_gemm<1, true ><<<dim3(256, 8), 256, SMEM_GEMM>>>(state, 64, W_heads, a_src, a_dst,
                                                       pWh, pss, psd);
    k_sort<0><<<BHv, 512>>>();
    k_attn<0><<<dim3(BHv, 8), 512, attn_smem>>>();
    k_gemm<8, false><<<256, 256, SMEM_GEMM>>>(px, 512, W_out, a_out_src, a_out_dst,
                                              pWh2, ps2s, ps2d);
    k_sort<1><<<Bv, 512>>>();
    k_attn<1><<<dim3(Bv, 8), 512, attn_smem>>>();
    k_fc1<<<dim3(64, 4), 256, 512*36*4>>>(fc1_w);
    k_fc1r<<<32, 256>>>(fc1_b);
    k_fc2<<<32, 256>>>(fc2_w, fc2_b);
    k_fc3<<<32, 128>>>(fc3_w, fc3_b, out);
}